// round 13
// baseline (speedup 1.0000x reference)
#include <cuda_runtime.h>
#include <cuda_fp16.h>
#include <math.h>
#include <stdint.h>

#define DMODEL 768
#define NH     8
#define DH     96
#define NLAYER 6
#define SPAN   512
#define SEQ    512
#define BATCH  8
#define PPOS   1024
#define FF     3072
#define NTOK   (BATCH*SEQ)
#define ZBAT   (BATCH*NH)
#define LN_EPS 1e-7f
#define NEGF   (-3.402823466e38f)
#define D3     (3*DMODEL)

// -------------------- scratch --------------------
__device__ float  g_h32 [NTOK*DMODEL];
__device__ __half g_h16 [NTOK*DMODEL];
__device__ __half g_qkv [(size_t)NTOK*D3];
__device__ __half g_ctx [NTOK*DMODEL];
__device__ __half g_tmp [NTOK*DMODEL];
__device__ __half g_wqkv[(size_t)NLAYER*DMODEL*D3];
__device__ float  g_bqkv[NLAYER*D3];
__device__ __half g_wi  [(size_t)NLAYER*DMODEL*FF];
__device__ __half g_wo2 [(size_t)NLAYER*FF*DMODEL];
__device__ __half g_wo  [(size_t)NLAYER*DMODEL*DMODEL];
__device__ __half g_wpk [(size_t)NLAYER*DMODEL*DMODEL];
__device__ __half g_wpq [(size_t)NLAYER*DMODEL*DMODEL];
__device__ __half g_rel [PPOS*DMODEL];
__device__ __half g_pk  [(size_t)NLAYER*PPOS*DMODEL];
__device__ __half g_pq  [(size_t)NLAYER*PPOS*DMODEL];
__device__ __half g_s1  [(size_t)ZBAT*SEQ*SEQ];
__device__ __half g_c2pg[(size_t)ZBAT*SEQ*SEQ];     // gathered [z][q][k]
__device__ __half g_p2c [(size_t)ZBAT*SEQ*PPOS];
__device__ __half g_ffn [(size_t)NTOK*FF];

// -------------------- helpers --------------------
__device__ __forceinline__ float gelu_f(float x) {
    return 0.5f * x * (1.0f + erff(x * 0.7071067811865475f));
}
__device__ __forceinline__ uint32_t smem_u32(const void* p) {
    uint32_t a;
    asm("{ .reg .u64 t; cvta.to.shared.u64 t, %1; cvt.u32.u64 %0, t; }" : "=r"(a) : "l"(p));
    return a;
}
__device__ __forceinline__ void mma_f16(float c[4], const uint32_t a[4], const uint32_t b[2]) {
    asm volatile(
        "mma.sync.aligned.m16n8k16.row.col.f32.f16.f16.f32 "
        "{%0,%1,%2,%3},{%4,%5,%6,%7},{%8,%9},{%0,%1,%2,%3};\n"
        : "+f"(c[0]), "+f"(c[1]), "+f"(c[2]), "+f"(c[3])
        : "r"(a[0]), "r"(a[1]), "r"(a[2]), "r"(a[3]), "r"(b[0]), "r"(b[1]));
}
__device__ __forceinline__ void ldsm_x4(uint32_t r[4], uint32_t addr) {
    asm volatile("ldmatrix.sync.aligned.m8n8.x4.shared.b16 {%0,%1,%2,%3}, [%4];"
        : "=r"(r[0]), "=r"(r[1]), "=r"(r[2]), "=r"(r[3]) : "r"(addr));
}
__device__ __forceinline__ void ldsm_x4t(uint32_t r[4], uint32_t addr) {
    asm volatile("ldmatrix.sync.aligned.m8n8.x4.trans.shared.b16 {%0,%1,%2,%3}, [%4];"
        : "=r"(r[0]), "=r"(r[1]), "=r"(r[2]), "=r"(r[3]) : "r"(addr));
}
__device__ __forceinline__ void cp16(uint32_t dst, const void* src) {
    asm volatile("cp.async.cg.shared.global [%0], [%1], 16;" :: "r"(dst), "l"(src));
}
#define CP_COMMIT() asm volatile("cp.async.commit_group;" ::: "memory")
#define CP_WAIT2()  asm volatile("cp.async.wait_group 2;" ::: "memory")

// ============================ cp.async FP16 mma GEMM ============================
// act: 0 = none, 1 = gelu, 2 = c2p-gather epilogue (write [q][k=q-d+512], ldc=SEQ)
template<int BM, int BN, int NWARP, bool BT>
__global__ void __launch_bounds__(NWARP*32, 2)
hgemm(const __half* __restrict__ A, const __half* __restrict__ B,
      const float* __restrict__ bias, __half* __restrict__ C,
      int K, int lda, int ldb, int ldc,
      long sAb, long sAh, long sBb, long sBh, long sBiasH,
      long sCb, long sCh, int act, int ntiles, int tpz, int tiles_x, int band)
{
    constexpr int THREADS = NWARP * 32;
    constexpr int WM = 64, WN = 32;
    constexpr int MI = WM / 16, NI = WN / 8;
    constexpr int WARPS_N = BN / WN;
    constexpr int ROWA = 80;
    constexpr int ASTG = BM * ROWA;
    constexpr int ROWB = BT ? 80 : (BN + 8) * 2;
    constexpr int BSTG = BT ? (BN * 80) : (32 * ROWB);
    constexpr int ACH  = BM * 4;
    constexpr int A_IT = (ACH + THREADS - 1) / THREADS;
    constexpr int BCHN = BN / 8;
    constexpr int BCH  = BT ? (BN * 4) : (32 * BCHN);
    constexpr int B_IT = (BCH + THREADS - 1) / THREADS;

    extern __shared__ char sm[];
    const uint32_t asb = smem_u32(sm);
    const uint32_t bsb = asb + 4 * ASTG;

    const int tid = threadIdx.x;
    const int wid = tid >> 5, lane = tid & 31;
    const int g = lane >> 2, tig = lane & 3;
    const int wm0 = (wid / WARPS_N) * WM, wn0 = (wid % WARPS_N) * WN;
    const int nk = K / 32;
    const long bAdv = BT ? 32 : (long)32 * ldb;

    const uint32_t aoff = (uint32_t)(lane & 15) * ROWA + (uint32_t)(lane >> 4) * 16;
    const uint32_t boffT = ((uint32_t)(lane & 7) + (uint32_t)((lane >> 4) & 1) * 8) * 80
                         + (uint32_t)((lane >> 3) & 1) * 16;
    const uint32_t boffN = ((uint32_t)(lane & 7) + (uint32_t)((lane >> 3) & 1) * 8) * ROWB
                         + (uint32_t)((lane >> 4) & 1) * 16;

    for (int T = blockIdx.x; T < ntiles; T += gridDim.x) {
        const int z = T / tpz, tl = T - z * tpz;
        int ty, tx;
        if (band == 0) { ty = tl / tiles_x; tx = tl - ty * tiles_x; }
        else { ty = tl / 5; int rr = tl - ty * 5; tx = (band == 1 ? ty : 3 - ty) + rr; }
        const int m0 = ty * BM, n0 = tx * BN;
        const int bb = z >> 3, hh = z & 7;
        const __half* Az = A + (size_t)bb * sAb + (size_t)hh * sAh;
        const __half* Bz = B + (size_t)bb * sBb + (size_t)hh * sBh;
        __half* Cz = C + (size_t)bb * sCb + (size_t)hh * sCh;
        const float* biasp = bias ? (bias + (size_t)hh * sBiasH) : nullptr;

        const __half* aS[A_IT]; uint32_t aD[A_IT];
        #pragma unroll
        for (int i = 0; i < A_IT; i++) {
            int lin = tid + i * THREADS;
            if ((ACH % THREADS == 0) || lin < ACH) {
                int r = lin >> 2, c = lin & 3;
                aS[i] = Az + (size_t)(m0 + r) * lda + c * 8;
                aD[i] = (uint32_t)r * ROWA + (uint32_t)c * 16;
            }
        }
        const __half* bS[B_IT]; uint32_t bD[B_IT];
        #pragma unroll
        for (int i = 0; i < B_IT; i++) {
            int lin = tid + i * THREADS;
            if ((BCH % THREADS == 0) || lin < BCH) {
                if (BT) {
                    int r = lin >> 2, c = lin & 3;
                    bS[i] = Bz + (size_t)(n0 + r) * ldb + c * 8;
                    bD[i] = (uint32_t)r * 80 + (uint32_t)c * 16;
                } else {
                    int kk = lin / BCHN, c = lin - kk * BCHN;
                    bS[i] = Bz + (size_t)kk * ldb + n0 + c * 8;
                    bD[i] = (uint32_t)kk * ROWB + (uint32_t)c * 16;
                }
            }
        }

        float acc[MI][NI][4];
        #pragma unroll
        for (int i = 0; i < MI; i++)
            #pragma unroll
            for (int j = 0; j < NI; j++)
                #pragma unroll
                for (int t = 0; t < 4; t++) acc[i][j][t] = 0.f;

        auto issue = [&](int s) {
            if (s < nk) {
                const uint32_t ab = asb + (s & 3) * ASTG;
                const uint32_t bbm = bsb + (s & 3) * BSTG;
                #pragma unroll
                for (int i = 0; i < A_IT; i++) {
                    int lin = tid + i * THREADS;
                    if ((ACH % THREADS == 0) || lin < ACH) {
                        cp16(ab + aD[i], aS[i]);
                        aS[i] += 32;
                    }
                }
                #pragma unroll
                for (int i = 0; i < B_IT; i++) {
                    int lin = tid + i * THREADS;
                    if ((BCH % THREADS == 0) || lin < BCH) {
                        cp16(bbm + bD[i], bS[i]);
                        bS[i] += bAdv;
                    }
                }
            }
            CP_COMMIT();
        };

        __syncthreads();
        issue(0); issue(1); issue(2);
        int fetch = 3;

        uint32_t aStg[4], bStg[4];
        #pragma unroll
        for (int b4 = 0; b4 < 4; b4++) {
            aStg[b4] = asb + (uint32_t)b4 * ASTG + (uint32_t)wm0 * ROWA + aoff;
            bStg[b4] = BT ? (bsb + (uint32_t)b4 * BSTG + (uint32_t)wn0 * 80 + boffT)
                          : (bsb + (uint32_t)b4 * BSTG + boffN + (uint32_t)wn0 * 2);
        }

        for (int it = 0; it < nk; it++) {
            CP_WAIT2();
            __syncthreads();
            issue(fetch); fetch++;
            const int buf = it & 3;
            const uint32_t aB = aStg[buf];
            const uint32_t bB = bStg[buf];
            #pragma unroll
            for (int ks = 0; ks < 2; ks++) {
                uint32_t af[MI][4], bf[NI][2];
                #pragma unroll
                for (int i = 0; i < MI; i++)
                    ldsm_x4(af[i], aB + (uint32_t)i * (16 * ROWA) + (uint32_t)ks * 32);
                if (BT) {
                    #pragma unroll
                    for (int jj = 0; jj < NI / 2; jj++) {
                        uint32_t t4[4];
                        ldsm_x4(t4, bB + (uint32_t)ks * 32 + (uint32_t)jj * (16 * 80));
                        bf[2 * jj][0] = t4[0]; bf[2 * jj][1] = t4[1];
                        bf[2 * jj + 1][0] = t4[2]; bf[2 * jj + 1][1] = t4[3];
                    }
                } else {
                    #pragma unroll
                    for (int jj = 0; jj < NI / 2; jj++) {
                        uint32_t t4[4];
                        ldsm_x4t(t4, bB + (uint32_t)(ks * 16) * ROWB + (uint32_t)jj * 32);
                        bf[2 * jj][0] = t4[0]; bf[2 * jj][1] = t4[1];
                        bf[2 * jj + 1][0] = t4[2]; bf[2 * jj + 1][1] = t4[3];
                    }
                }
                #pragma unroll
                for (int i = 0; i < MI; i++)
                    #pragma unroll
                    for (int j = 0; j < NI; j++)
                        mma_f16(acc[i][j], af[i], bf[j]);
            }
        }

        if (act == 2) {
            // c2p gather: value at (q=r, d=col) -> out[q][k] with k = q - d + SPAN
            #pragma unroll
            for (int i = 0; i < MI; i++) {
                int r0 = m0 + wm0 + 16 * i + g;
                #pragma unroll
                for (int j = 0; j < NI; j++) {
                    int col = n0 + wn0 + 8 * j + 2 * tig;
                    int k0e = r0 - col + SPAN;
                    if ((unsigned)k0e < SEQ)
                        Cz[(size_t)r0 * ldc + k0e] = __float2half(acc[i][j][0]);
                    if ((unsigned)(k0e - 1) < SEQ)
                        Cz[(size_t)r0 * ldc + k0e - 1] = __float2half(acc[i][j][1]);
                    if ((unsigned)(k0e + 8) < SEQ)
                        Cz[(size_t)(r0 + 8) * ldc + k0e + 8] = __float2half(acc[i][j][2]);
                    if ((unsigned)(k0e + 7) < SEQ)
                        Cz[(size_t)(r0 + 8) * ldc + k0e + 7] = __float2half(acc[i][j][3]);
                }
            }
        } else {
            #pragma unroll
            for (int i = 0; i < MI; i++) {
                int r0 = m0 + wm0 + 16 * i + g;
                #pragma unroll
                for (int j = 0; j < NI; j++) {
                    int col = n0 + wn0 + 8 * j + 2 * tig;
                    float b0v = biasp ? biasp[col] : 0.f;
                    float b1v = biasp ? biasp[col + 1] : 0.f;
                    float v0 = acc[i][j][0] + b0v, v1 = acc[i][j][1] + b1v;
                    float v2 = acc[i][j][2] + b0v, v3 = acc[i][j][3] + b1v;
                    if (act == 1) { v0 = gelu_f(v0); v1 = gelu_f(v1); v2 = gelu_f(v2); v3 = gelu_f(v3); }
                    *reinterpret_cast<__half2*>(Cz + (size_t)r0 * ldc + col) = __floats2half2_rn(v0, v1);
                    *reinterpret_cast<__half2*>(Cz + (size_t)(r0 + 8) * ldc + col) = __floats2half2_rn(v2, v3);
                }
            }
        }
    }
}

// -------------------- fused prologue: ONE launch for all weight prep --------------------
__global__ void prep_all(const float* __restrict__ Wq, const float* __restrict__ Wk,
                         const float* __restrict__ Wv, const float* __restrict__ bq,
                         const float* __restrict__ bk, const float* __restrict__ bv,
                         const float* __restrict__ Wi, const float* __restrict__ Wo2,
                         const float* __restrict__ Wo, const float* __restrict__ Wpk,
                         const float* __restrict__ Wpq, const float* __restrict__ rel_emb,
                         __half* __restrict__ wqkv, float* __restrict__ bqkv,
                         __half* __restrict__ wi, __half* __restrict__ wo2,
                         __half* __restrict__ wo, __half* __restrict__ wpk,
                         __half* __restrict__ wpq, __half* __restrict__ rel)
{
    const long N1 = (long)NLAYER * DMODEL * D3;
    const long N2 = (long)NLAYER * DMODEL * FF;
    const long N4 = (long)NLAYER * DMODEL * DMODEL;
    const long N7 = (long)PPOS * DMODEL;
    const long N8 = (long)NLAYER * D3;
    long e = ((long)blockIdx.x * blockDim.x + threadIdx.x) * 4;
    const float* src; __half* dst; long i;
    if (e < N1) {
        i = e;
        int l = (int)(i / ((long)DMODEL * D3));
        long r = i - (long)l * DMODEL * D3;
        int row = (int)(r / D3), col = (int)(r - (long)row * D3);
        const float* s2; int c;
        if (col < DMODEL)        { s2 = Wq; c = col; }
        else if (col < 2*DMODEL) { s2 = Wk; c = col - DMODEL; }
        else                     { s2 = Wv; c = col - 2*DMODEL; }
        float4 v = *reinterpret_cast<const float4*>(s2 + ((size_t)l * DMODEL + row) * DMODEL + c);
        wqkv[i] = __float2half(v.x); wqkv[i+1] = __float2half(v.y);
        wqkv[i+2] = __float2half(v.z); wqkv[i+3] = __float2half(v.w);
        return;
    }
    e -= N1;
    if (e < N2)      { src = Wi;  dst = wi;  i = e; }
    else if ((e -= N2) < N2) { src = Wo2; dst = wo2; i = e; }
    else if ((e -= N2) < N4) { src = Wo;  dst = wo;  i = e; }
    else if ((e -= N4) < N4) { src = Wpk; dst = wpk; i = e; }
    else if ((e -= N4) < N4) { src = Wpq; dst = wpq; i = e; }
    else if ((e -= N4) < N7) { src = rel_emb; dst = rel; i = e; }
    else {
        e -= N7;
        if (e < N8) {
            #pragma unroll
            for (int t = 0; t < 4; t++) {
                long idx = e + t;
                int l = (int)(idx / D3), col = (int)(idx - (long)l * D3);
                const float* s2; int c;
                if (col < DMODEL)        { s2 = bq; c = col; }
                else if (col < 2*DMODEL) { s2 = bk; c = col - DMODEL; }
                else                     { s2 = bv; c = col - 2*DMODEL; }
                bqkv[idx] = s2[(size_t)l * DMODEL + c];
            }
        }
        return;
    }
    float4 v = *reinterpret_cast<const float4*>(src + i);
    dst[i] = __float2half(v.x); dst[i+1] = __float2half(v.y);
    dst[i+2] = __float2half(v.z); dst[i+3] = __float2half(v.w);
}

// -------------------- block reductions (256 threads) --------------------
__device__ __forceinline__ float blk_sum256(float v) {
    __shared__ float sh[8];
    __syncthreads();
    for (int o = 16; o > 0; o >>= 1) v += __shfl_down_sync(0xffffffffu, v, o);
    if ((threadIdx.x & 31) == 0) sh[threadIdx.x >> 5] = v;
    __syncthreads();
    if (threadIdx.x == 0) {
        float s = 0.f;
        #pragma unroll
        for (int i = 0; i < 8; i++) s += sh[i];
        sh[0] = s;
    }
    __syncthreads();
    return sh[0];
}
__device__ __forceinline__ float blk_max256(float v) {
    __shared__ float sh[8];
    __syncthreads();
    for (int o = 16; o > 0; o >>= 1) v = fmaxf(v, __shfl_down_sync(0xffffffffu, v, o));
    if ((threadIdx.x & 31) == 0) sh[threadIdx.x >> 5] = v;
    __syncthreads();
    if (threadIdx.x == 0) {
        float s = sh[0];
        #pragma unroll
        for (int i = 1; i < 8; i++) s = fmaxf(s, sh[i]);
        sh[0] = s;
    }
    __syncthreads();
    return sh[0];
}

// ------------- combine rel-pos biases + mask + softmax (f16 in place) -----------
__global__ void combine_softmax(__half* __restrict__ s1, const __half* __restrict__ c2pg,
                                const __half* __restrict__ p2c, const int* __restrict__ amask)
{
    const int q = blockIdx.x, z = blockIdx.y, b = z >> 3;
    const float inv_scale = 0.05892556509887896f;   // 1/sqrt(288)
    __half* srow = s1 + ((size_t)z * SEQ + q) * SEQ;
    const __half* crow = c2pg + ((size_t)z * SEQ + q) * SEQ;
    const __half* pz   = p2c + (size_t)z * SEQ * PPOS;
    const int mq = amask[b * SEQ + q];
    float vals[2];
    #pragma unroll
    for (int i = 0; i < 2; i++) {
        int k = threadIdx.x + i * 256;
        int d = q - k + SPAN;
        float s = (__half2float(srow[k]) + __half2float(crow[k])
                 + __half2float(pz[(size_t)k * PPOS + d])) * inv_scale;
        int mk = amask[b * SEQ + k];
        vals[i] = (mq * mk > 0) ? s : NEGF;
    }
    float mx = blk_max256(fmaxf(vals[0], vals[1]));
    float e0 = __expf(vals[0] - mx), e1 = __expf(vals[1] - mx);
    float inv = 1.0f / blk_sum256(e0 + e1);
    srow[threadIdx.x]       = __float2half(e0 * inv);
    srow[threadIdx.x + 256] = __float2half(e1 * inv);
}

// ---------------- LayerNorm ----------------
__global__ void embed_ln(const float* __restrict__ x, const float* __restrict__ pos,
                         const float* __restrict__ g, const float* __restrict__ beta,
                         const int* __restrict__ amask, float* __restrict__ outF,
                         __half* __restrict__ outH)
{
    const int row = blockIdx.x, s = row & (SEQ - 1);
    float v[3], partial = 0.f;
    #pragma unroll
    for (int i = 0; i < 3; i++) {
        int j = threadIdx.x + i * 256;
        v[i] = x[(size_t)row * DMODEL + j] + pos[(size_t)s * DMODEL + j];
        partial += v[i];
    }
    float mean = blk_sum256(partial) * (1.0f / DMODEL);
    float p2 = 0.f;
    #pragma unroll
    for (int i = 0; i < 3; i++) { float d = v[i] - mean; p2 += d * d; }
    float rstd = rsqrtf(blk_sum256(p2) * (1.0f / DMODEL) + LN_EPS);
    float mf = (float)amask[row];
    #pragma unroll
    for (int i = 0; i < 3; i++) {
        int j = threadIdx.x + i * 256;
        float o = ((v[i] - mean) * rstd * g[j] + beta[j]) * mf;
        outF[(size_t)row * DMODEL + j] = o;
        outH[(size_t)row * DMODEL + j] = __float2half(o);
    }
}

__global__ void add_ln(const __half* __restrict__ a, const float* __restrict__ res,
                       const float* __restrict__ g, const float* __restrict__ beta,
                       float* __restrict__ outF, __half* __restrict__ outH)
{
    const int row = blockIdx.x;
    float v[3], partial = 0.f;
    #pragma unroll
    for (int i = 0; i < 3; i++) {
        int j = threadIdx.x + i * 256;
        v[i] = __half2float(a[(size_t)row * DMODEL + j]) + res[(size_t)row * DMODEL + j];
        partial += v[i];
    }
    float mean = blk_sum256(partial) * (1.0f / DMODEL);
    float p2 = 0.f;
    #pragma unroll
    for (int i = 0; i < 3; i++) { float d = v[i] - mean; p2 += d * d; }
    float rstd = rsqrtf(blk_sum256(p2) * (1.0f / DMODEL) + LN_EPS);
    #pragma unroll
    for (int i = 0; i < 3; i++) {
        int j = threadIdx.x + i * 256;
        float o = (v[i] - mean) * rstd * g[j] + beta[j];
        outF[(size_t)row * DMODEL + j] = o;
        outH[(size_t)row * DMODEL + j] = __float2half(o);
    }
}

// ==================================== launcher ====================================
static inline int pgrid(int tiles, int cap) { return tiles < cap ? tiles : cap; }

extern "C" void kernel_launch(void* const* d_in, const int* in_sizes, int n_in,
                              void* d_out, int out_size)
{
    const float* x       = (const float*)d_in[0];
    const float* pos_emb = (const float*)d_in[1];
    const float* rel_emb = (const float*)d_in[2];
    const float* ln_e_g  = (const float*)d_in[3];
    const float* ln_e_b  = (const float*)d_in[4];
    const float* Wq  = (const float*)d_in[5];
    const float* bq  = (const float*)d_in[6];
    const float* Wk  = (const float*)d_in[7];
    const float* bk  = (const float*)d_in[8];
    const float* Wv  = (const float*)d_in[9];
    const float* bv  = (const float*)d_in[10];
    const float* Wo  = (const float*)d_in[11];
    const float* bo  = (const float*)d_in[12];
    const float* Wpk = (const float*)d_in[13];
    const float* bpk = (const float*)d_in[14];
    const float* Wpq = (const float*)d_in[15];
    const float* bpq = (const float*)d_in[16];
    const float* ln1g = (const float*)d_in[17];
    const float* ln1b = (const float*)d_in[18];
    const float* Wi   = (const float*)d_in[19];
    const float* bi   = (const float*)d_in[20];
    const float* Wo2  = (const float*)d_in[21];
    const float* bo2  = (const float*)d_in[22];
    const float* ln2g = (const float*)d_in[23];
    const float* ln2b = (const float*)d_in[24];
    const int*   amask = (const int*)d_in[25];

    float *h32, *bqkv;
    __half *h16, *qkv, *ctx, *tmp, *wqkv, *wi, *wo2, *wo, *wpk, *wpq, *rel;
    __half *pk, *pq, *s1, *c2pg, *p2c, *ffn;
    cudaGetSymbolAddress((void**)&h32,  g_h32);
    cudaGetSymbolAddress((void**)&h16,  g_h16);
    cudaGetSymbolAddress((void**)&qkv,  g_qkv);
    cudaGetSymbolAddress((void**)&ctx,  g_ctx);
    cudaGetSymbolAddress((void**)&tmp,  g_tmp);
    cudaGetSymbolAddress((void**)&wqkv, g_wqkv);
    cudaGetSymbolAddress((void**)&bqkv, g_bqkv);
    cudaGetSymbolAddress((void**)&wi,   g_wi);
    cudaGetSymbolAddress((void**)&wo2,  g_wo2);
    cudaGetSymbolAddress((void**)&wo,   g_wo);
    cudaGetSymbolAddress((void**)&wpk,  g_wpk);
    cudaGetSymbolAddress((void**)&wpq,  g_wpq);
    cudaGetSymbolAddress((void**)&rel,  g_rel);
    cudaGetSymbolAddress((void**)&pk,   g_pk);
    cudaGetSymbolAddress((void**)&pq,   g_pq);
    cudaGetSymbolAddress((void**)&s1,   g_s1);
    cudaGetSymbolAddress((void**)&c2pg, g_c2pg);
    cudaGetSymbolAddress((void**)&p2c,  g_p2c);
    cudaGetSymbolAddress((void**)&ffn,  g_ffn);

    const long DD = (long)DMODEL * DMODEL;
    const long S2 = (long)SEQ * SEQ;
    const long SP = (long)SEQ * PPOS;
    const long SD3 = (long)SEQ * D3;
    const long PD = (long)PPOS * DMODEL;
    const int CAP = 296;

    const int SM_NN128 = 4 * 128 * 80 + 4 * 32 * 272;   // 75776
    const int SM_NT128 = 4 * 128 * 80 + 4 * 128 * 80;   // 81920
    const int SM_NN96  = 4 * 128 * 80 + 4 * 32 * 208;   // 67584
    cudaFuncSetAttribute(hgemm<128,128,8,false>, cudaFuncAttributeMaxDynamicSharedMemorySize, SM_NN128);
    cudaFuncSetAttribute(hgemm<128,128,8,true>,  cudaFuncAttributeMaxDynamicSharedMemorySize, SM_NT128);
    cudaFuncSetAttribute(hgemm<128,96,6,false>,  cudaFuncAttributeMaxDynamicSharedMemorySize, SM_NN96);

    // ---- fused prologue (1 launch) ----
    {
        long total = (long)NLAYER*DMODEL*D3 + 2L*NLAYER*DMODEL*FF + 3L*NLAYER*DD
                   + (long)PPOS*DMODEL + (long)NLAYER*D3;
        prep_all<<<(unsigned)((total / 4 + 255) / 256), 256>>>(
            Wq, Wk, Wv, bq, bk, bv, Wi, Wo2, Wo, Wpk, Wpq, rel_emb,
            wqkv, bqkv, wi, wo2, wo, wpk, wpq, rel);
    }
    embed_ln<<<NTOK, 256>>>(x, pos_emb, ln_e_g, ln_e_b, amask, h32, h16);

    // pos projections, all layers (z = layer): 48 tiles/z
    hgemm<128,128,8,false><<<pgrid(288, CAP), 256, SM_NN128>>>(
        rel, wpk, bpk, pk, DMODEL, DMODEL, DMODEL, DMODEL,
        0, 0, 0, DD, DMODEL, 0, PD, 0, 288, 48, 6, 0);
    hgemm<128,128,8,false><<<pgrid(288, CAP), 256, SM_NN128>>>(
        rel, wpq, bpq, pq, DMODEL, DMODEL, DMODEL, DMODEL,
        0, 0, 0, DD, DMODEL, 0, PD, 0, 288, 48, 6, 0);

    for (int l = 0; l < NLAYER; l++) {
        // fused QKV: 576 tiles
        hgemm<128,128,8,false><<<pgrid(576, CAP), 256, SM_NN128>>>(
            h16, wqkv + (size_t)l * DMODEL * D3, bqkv + (size_t)l * D3, qkv,
            DMODEL, DMODEL, D3, D3, 0,0,0,0,0, 0,0, 0, 576, 576, 18, 0);

        // scores = Q @ K^T
        hgemm<128,128,8,true><<<pgrid(1024, CAP), 256, SM_NT128>>>(
            qkv, qkv + DMODEL, nullptr, s1, DH, D3, D3, SEQ,
            SD3, DH, SD3, DH, 0, 8*S2, S2, 0, 1024, 16, 4, 0);
        // c2p = Q @ PK^T (banded, gather epilogue -> [z][q][k])
        hgemm<128,128,8,true><<<pgrid(1280, CAP), 256, SM_NT128>>>(
            qkv, pk + (size_t)l * PD, nullptr, c2pg, DH, D3, DMODEL, SEQ,
            SD3, DH, 0, DH, 0, 8*S2, S2, 2, 1280, 20, 0, 1);
        // p2c = K @ PQ^T (banded)
        hgemm<128,128,8,true><<<pgrid(1280, CAP), 256, SM_NT128>>>(
            qkv + DMODEL, pq + (size_t)l * PD, nullptr, p2c, DH, D3, DMODEL, PPOS,
            SD3, DH, 0, DH, 0, 8*SP, SP, 0, 1280, 20, 0, 2);

        combine_softmax<<<dim3(SEQ, ZBAT), 256>>>(s1, c2pg, p2c, amask);

        // ctx = probs @ V -> [b, q, h*96+d]
        hgemm<128,96,6,false><<<pgrid(256, CAP), 192, SM_NN96>>>(
            s1, qkv + 2*DMODEL, nullptr, ctx, SEQ, SEQ, D3, DMODEL,
            8*S2, S2, SD3, DH, 0, (long)SEQ*DMODEL, DH, 0, 256, 4, 1, 0);

        // attn out proj: 192 tiles
        hgemm<128,128,8,false><<<pgrid(192, CAP), 256, SM_NN128>>>(
            ctx, wo + (size_t)l*DD, bo + (size_t)l*DMODEL, tmp,
            DMODEL, DMODEL, DMODEL, DMODEL, 0,0,0,0,0, 0,0, 0, 192, 192, 6, 0);
        add_ln<<<NTOK, 256>>>(tmp, h32, ln1g + (size_t)l*DMODEL, ln1b + (size_t)l*DMODEL, h32, h16);

        // FFN1 (gelu): 768 tiles
        hgemm<128,128,8,false><<<pgrid(768, CAP), 256, SM_NN128>>>(
            h16, wi + (size_t)l*DMODEL*FF, bi + (size_t)l*FF, ffn,
            DMODEL, DMODEL, FF, FF, 0,0,0,0,0, 0,0, 1, 768, 768, 24, 0);
        // FFN2: K=3072, 192 tiles
        hgemm<128,128,8,false><<<pgrid(192, CAP), 256, SM_NN128>>>(
            ffn, wo2 + (size_t)l*FF*DMODEL, bo2 + (size_t)l*DMODEL, tmp,
            FF, FF, DMODEL, DMODEL, 0,0,0,0,0, 0,0, 0, 192, 192, 6, 0);

        float* outF = (l == NLAYER - 1) ? (float*)d_out : h32;
        add_ln<<<NTOK, 256>>>(tmp, h32, ln2g + (size_t)l*DMODEL, ln2b + (size_t)l*DMODEL, outF, h16);
    }
}

// round 14
// speedup vs baseline: 1.1826x; 1.1826x over previous
#include <cuda_runtime.h>
#include <cuda_fp16.h>
#include <math.h>
#include <stdint.h>

#define DMODEL 768
#define NH     8
#define DH     96
#define NLAYER 6
#define SPAN   512
#define SEQ    512
#define BATCH  8
#define PPOS   1024
#define FF     3072
#define NTOK   (BATCH*SEQ)
#define ZBAT   (BATCH*NH)
#define LN_EPS 1e-7f
#define NEGF   (-3.402823466e38f)
#define D3     (3*DMODEL)

// -------------------- scratch --------------------
__device__ float  g_h32 [NTOK*DMODEL];
__device__ __half g_h16 [NTOK*DMODEL];
__device__ __half g_qkv [(size_t)NTOK*D3];
__device__ __half g_ctx [NTOK*DMODEL];
__device__ __half g_tmp [NTOK*DMODEL];
__device__ __half g_wqkv[(size_t)NLAYER*DMODEL*D3];
__device__ float  g_bqkv[NLAYER*D3];
__device__ __half g_wi  [(size_t)NLAYER*DMODEL*FF];
__device__ __half g_wo2 [(size_t)NLAYER*FF*DMODEL];
__device__ __half g_wo  [(size_t)NLAYER*DMODEL*DMODEL];
__device__ __half g_wpk [(size_t)NLAYER*DMODEL*DMODEL];
__device__ __half g_wpq [(size_t)NLAYER*DMODEL*DMODEL];
__device__ __half g_rel [PPOS*DMODEL];
__device__ __half g_pk  [(size_t)NLAYER*PPOS*DMODEL];
__device__ __half g_pq  [(size_t)NLAYER*PPOS*DMODEL];
__device__ __half g_s1  [(size_t)ZBAT*SEQ*SEQ];
__device__ __half g_c2p [(size_t)ZBAT*SEQ*PPOS];
__device__ __half g_p2c [(size_t)ZBAT*SEQ*PPOS];
__device__ __half g_ffn [(size_t)NTOK*FF];

// -------------------- helpers --------------------
__device__ __forceinline__ float gelu_f(float x) {
    return 0.5f * x * (1.0f + erff(x * 0.7071067811865475f));
}
__device__ __forceinline__ uint32_t smem_u32(const void* p) {
    uint32_t a;
    asm("{ .reg .u64 t; cvta.to.shared.u64 t, %1; cvt.u32.u64 %0, t; }" : "=r"(a) : "l"(p));
    return a;
}
__device__ __forceinline__ void mma_f16(float c[4], const uint32_t a[4], const uint32_t b[2]) {
    asm volatile(
        "mma.sync.aligned.m16n8k16.row.col.f32.f16.f16.f32 "
        "{%0,%1,%2,%3},{%4,%5,%6,%7},{%8,%9},{%0,%1,%2,%3};\n"
        : "+f"(c[0]), "+f"(c[1]), "+f"(c[2]), "+f"(c[3])
        : "r"(a[0]), "r"(a[1]), "r"(a[2]), "r"(a[3]), "r"(b[0]), "r"(b[1]));
}
__device__ __forceinline__ void ldsm_x4(uint32_t r[4], uint32_t addr) {
    asm volatile("ldmatrix.sync.aligned.m8n8.x4.shared.b16 {%0,%1,%2,%3}, [%4];"
        : "=r"(r[0]), "=r"(r[1]), "=r"(r[2]), "=r"(r[3]) : "r"(addr));
}
__device__ __forceinline__ void ldsm_x4t(uint32_t r[4], uint32_t addr) {
    asm volatile("ldmatrix.sync.aligned.m8n8.x4.trans.shared.b16 {%0,%1,%2,%3}, [%4];"
        : "=r"(r[0]), "=r"(r[1]), "=r"(r[2]), "=r"(r[3]) : "r"(addr));
}
__device__ __forceinline__ void cp16(uint32_t dst, const void* src) {
    asm volatile("cp.async.cg.shared.global [%0], [%1], 16;" :: "r"(dst), "l"(src));
}
#define CP_COMMIT() asm volatile("cp.async.commit_group;" ::: "memory")
#define CP_WAIT2()  asm volatile("cp.async.wait_group 2;" ::: "memory")

// ============================ cp.async FP16 mma GEMM (Round-10 proven) ============================
template<int BM, int BN, int NWARP, bool BT>
__global__ void __launch_bounds__(NWARP*32, 2)
hgemm(const __half* __restrict__ A, const __half* __restrict__ B,
      const float* __restrict__ bias, __half* __restrict__ C,
      int K, int lda, int ldb, int ldc,
      long sAb, long sAh, long sBb, long sBh, long sBiasH,
      long sCb, long sCh, int act, int ntiles, int tpz, int tiles_x, int band)
{
    constexpr int THREADS = NWARP * 32;
    constexpr int WM = 64, WN = 32;
    constexpr int MI = WM / 16, NI = WN / 8;
    constexpr int WARPS_N = BN / WN;
    constexpr int ROWA = 80;
    constexpr int ASTG = BM * ROWA;
    constexpr int ROWB = BT ? 80 : (BN + 8) * 2;
    constexpr int BSTG = BT ? (BN * 80) : (32 * ROWB);
    constexpr int ACH  = BM * 4;
    constexpr int A_IT = (ACH + THREADS - 1) / THREADS;
    constexpr int BCHN = BN / 8;
    constexpr int BCH  = BT ? (BN * 4) : (32 * BCHN);
    constexpr int B_IT = (BCH + THREADS - 1) / THREADS;

    extern __shared__ char sm[];
    const uint32_t asb = smem_u32(sm);
    const uint32_t bsb = asb + 4 * ASTG;

    const int tid = threadIdx.x;
    const int wid = tid >> 5, lane = tid & 31;
    const int g = lane >> 2, tig = lane & 3;
    const int wm0 = (wid / WARPS_N) * WM, wn0 = (wid % WARPS_N) * WN;
    const int nk = K / 32;
    const long bAdv = BT ? 32 : (long)32 * ldb;

    const uint32_t aoff = (uint32_t)(lane & 15) * ROWA + (uint32_t)(lane >> 4) * 16;
    const uint32_t boffT = ((uint32_t)(lane & 7) + (uint32_t)((lane >> 4) & 1) * 8) * 80
                         + (uint32_t)((lane >> 3) & 1) * 16;
    const uint32_t boffN = ((uint32_t)(lane & 7) + (uint32_t)((lane >> 3) & 1) * 8) * ROWB
                         + (uint32_t)((lane >> 4) & 1) * 16;

    for (int T = blockIdx.x; T < ntiles; T += gridDim.x) {
        const int z = T / tpz, tl = T - z * tpz;
        int ty, tx;
        if (band == 0) { ty = tl / tiles_x; tx = tl - ty * tiles_x; }
        else { ty = tl / 5; int rr = tl - ty * 5; tx = (band == 1 ? ty : 3 - ty) + rr; }
        const int m0 = ty * BM, n0 = tx * BN;
        const int bb = z >> 3, hh = z & 7;
        const __half* Az = A + (size_t)bb * sAb + (size_t)hh * sAh;
        const __half* Bz = B + (size_t)bb * sBb + (size_t)hh * sBh;
        __half* Cz = C + (size_t)bb * sCb + (size_t)hh * sCh;
        const float* biasp = bias ? (bias + (size_t)hh * sBiasH) : nullptr;

        const __half* aS[A_IT]; uint32_t aD[A_IT];
        #pragma unroll
        for (int i = 0; i < A_IT; i++) {
            int lin = tid + i * THREADS;
            if ((ACH % THREADS == 0) || lin < ACH) {
                int r = lin >> 2, c = lin & 3;
                aS[i] = Az + (size_t)(m0 + r) * lda + c * 8;
                aD[i] = (uint32_t)r * ROWA + (uint32_t)c * 16;
            }
        }
        const __half* bS[B_IT]; uint32_t bD[B_IT];
        #pragma unroll
        for (int i = 0; i < B_IT; i++) {
            int lin = tid + i * THREADS;
            if ((BCH % THREADS == 0) || lin < BCH) {
                if (BT) {
                    int r = lin >> 2, c = lin & 3;
                    bS[i] = Bz + (size_t)(n0 + r) * ldb + c * 8;
                    bD[i] = (uint32_t)r * 80 + (uint32_t)c * 16;
                } else {
                    int kk = lin / BCHN, c = lin - kk * BCHN;
                    bS[i] = Bz + (size_t)kk * ldb + n0 + c * 8;
                    bD[i] = (uint32_t)kk * ROWB + (uint32_t)c * 16;
                }
            }
        }

        float acc[MI][NI][4];
        #pragma unroll
        for (int i = 0; i < MI; i++)
            #pragma unroll
            for (int j = 0; j < NI; j++)
                #pragma unroll
                for (int t = 0; t < 4; t++) acc[i][j][t] = 0.f;

        auto issue = [&](int s) {
            if (s < nk) {
                const uint32_t ab = asb + (s & 3) * ASTG;
                const uint32_t bbm = bsb + (s & 3) * BSTG;
                #pragma unroll
                for (int i = 0; i < A_IT; i++) {
                    int lin = tid + i * THREADS;
                    if ((ACH % THREADS == 0) || lin < ACH) {
                        cp16(ab + aD[i], aS[i]);
                        aS[i] += 32;
                    }
                }
                #pragma unroll
                for (int i = 0; i < B_IT; i++) {
                    int lin = tid + i * THREADS;
                    if ((BCH % THREADS == 0) || lin < BCH) {
                        cp16(bbm + bD[i], bS[i]);
                        bS[i] += bAdv;
                    }
                }
            }
            CP_COMMIT();
        };

        __syncthreads();
        issue(0); issue(1); issue(2);
        int fetch = 3;

        uint32_t aStg[4], bStg[4];
        #pragma unroll
        for (int b4 = 0; b4 < 4; b4++) {
            aStg[b4] = asb + (uint32_t)b4 * ASTG + (uint32_t)wm0 * ROWA + aoff;
            bStg[b4] = BT ? (bsb + (uint32_t)b4 * BSTG + (uint32_t)wn0 * 80 + boffT)
                          : (bsb + (uint32_t)b4 * BSTG + boffN + (uint32_t)wn0 * 2);
        }

        for (int it = 0; it < nk; it++) {
            CP_WAIT2();
            __syncthreads();
            issue(fetch); fetch++;
            const int buf = it & 3;
            const uint32_t aB = aStg[buf];
            const uint32_t bB = bStg[buf];
            #pragma unroll
            for (int ks = 0; ks < 2; ks++) {
                uint32_t af[MI][4], bf[NI][2];
                #pragma unroll
                for (int i = 0; i < MI; i++)
                    ldsm_x4(af[i], aB + (uint32_t)i * (16 * ROWA) + (uint32_t)ks * 32);
                if (BT) {
                    #pragma unroll
                    for (int jj = 0; jj < NI / 2; jj++) {
                        uint32_t t4[4];
                        ldsm_x4(t4, bB + (uint32_t)ks * 32 + (uint32_t)jj * (16 * 80));
                        bf[2 * jj][0] = t4[0]; bf[2 * jj][1] = t4[1];
                        bf[2 * jj + 1][0] = t4[2]; bf[2 * jj + 1][1] = t4[3];
                    }
                } else {
                    #pragma unroll
                    for (int jj = 0; jj < NI / 2; jj++) {
                        uint32_t t4[4];
                        ldsm_x4t(t4, bB + (uint32_t)(ks * 16) * ROWB + (uint32_t)jj * 32);
                        bf[2 * jj][0] = t4[0]; bf[2 * jj][1] = t4[1];
                        bf[2 * jj + 1][0] = t4[2]; bf[2 * jj + 1][1] = t4[3];
                    }
                }
                #pragma unroll
                for (int i = 0; i < MI; i++)
                    #pragma unroll
                    for (int j = 0; j < NI; j++)
                        mma_f16(acc[i][j], af[i], bf[j]);
            }
        }

        // epilogue -> f16
        #pragma unroll
        for (int i = 0; i < MI; i++) {
            int r0 = m0 + wm0 + 16 * i + g;
            #pragma unroll
            for (int j = 0; j < NI; j++) {
                int col = n0 + wn0 + 8 * j + 2 * tig;
                float b0v = biasp ? biasp[col] : 0.f;
                float b1v = biasp ? biasp[col + 1] : 0.f;
                float v0 = acc[i][j][0] + b0v, v1 = acc[i][j][1] + b1v;
                float v2 = acc[i][j][2] + b0v, v3 = acc[i][j][3] + b1v;
                if (act == 1) { v0 = gelu_f(v0); v1 = gelu_f(v1); v2 = gelu_f(v2); v3 = gelu_f(v3); }
                *reinterpret_cast<__half2*>(Cz + (size_t)r0 * ldc + col) = __floats2half2_rn(v0, v1);
                *reinterpret_cast<__half2*>(Cz + (size_t)(r0 + 8) * ldc + col) = __floats2half2_rn(v2, v3);
            }
        }
    }
}

// -------------------- fused prologue: ONE launch for all weight prep --------------------
__global__ void prep_all(const float* __restrict__ Wq, const float* __restrict__ Wk,
                         const float* __restrict__ Wv, const float* __restrict__ bq,
                         const float* __restrict__ bk, const float* __restrict__ bv,
                         const float* __restrict__ Wi, const float* __restrict__ Wo2,
                         const float* __restrict__ Wo, const float* __restrict__ Wpk,
                         const float* __restrict__ Wpq, const float* __restrict__ rel_emb,
                         __half* __restrict__ wqkv, float* __restrict__ bqkv,
                         __half* __restrict__ wi, __half* __restrict__ wo2,
                         __half* __restrict__ wo, __half* __restrict__ wpk,
                         __half* __restrict__ wpq, __half* __restrict__ rel)
{
    const long N1 = (long)NLAYER * DMODEL * D3;
    const long N2 = (long)NLAYER * DMODEL * FF;
    const long N4 = (long)NLAYER * DMODEL * DMODEL;
    const long N7 = (long)PPOS * DMODEL;
    const long N8 = (long)NLAYER * D3;
    long e = ((long)blockIdx.x * blockDim.x + threadIdx.x) * 4;
    const float* src; __half* dst; long i;
    if (e < N1) {
        i = e;
        int l = (int)(i / ((long)DMODEL * D3));
        long r = i - (long)l * DMODEL * D3;
        int row = (int)(r / D3), col = (int)(r - (long)row * D3);
        const float* s2; int c;
        if (col < DMODEL)        { s2 = Wq; c = col; }
        else if (col < 2*DMODEL) { s2 = Wk; c = col - DMODEL; }
        else                     { s2 = Wv; c = col - 2*DMODEL; }
        float4 v = *reinterpret_cast<const float4*>(s2 + ((size_t)l * DMODEL + row) * DMODEL + c);
        wqkv[i] = __float2half(v.x); wqkv[i+1] = __float2half(v.y);
        wqkv[i+2] = __float2half(v.z); wqkv[i+3] = __float2half(v.w);
        return;
    }
    e -= N1;
    if (e < N2)      { src = Wi;  dst = wi;  i = e; }
    else if ((e -= N2) < N2) { src = Wo2; dst = wo2; i = e; }
    else if ((e -= N2) < N4) { src = Wo;  dst = wo;  i = e; }
    else if ((e -= N4) < N4) { src = Wpk; dst = wpk; i = e; }
    else if ((e -= N4) < N4) { src = Wpq; dst = wpq; i = e; }
    else if ((e -= N4) < N7) { src = rel_emb; dst = rel; i = e; }
    else {
        e -= N7;
        if (e < N8) {
            #pragma unroll
            for (int t = 0; t < 4; t++) {
                long idx = e + t;
                int l = (int)(idx / D3), col = (int)(idx - (long)l * D3);
                const float* s2; int c;
                if (col < DMODEL)        { s2 = bq; c = col; }
                else if (col < 2*DMODEL) { s2 = bk; c = col - DMODEL; }
                else                     { s2 = bv; c = col - 2*DMODEL; }
                bqkv[idx] = s2[(size_t)l * DMODEL + c];
            }
        }
        return;
    }
    float4 v = *reinterpret_cast<const float4*>(src + i);
    dst[i] = __float2half(v.x); dst[i+1] = __float2half(v.y);
    dst[i+2] = __float2half(v.z); dst[i+3] = __float2half(v.w);
}

// -------------------- warp reductions --------------------
__device__ __forceinline__ float warp_sum(float v) {
    #pragma unroll
    for (int o = 16; o > 0; o >>= 1) v += __shfl_xor_sync(0xffffffffu, v, o);
    return v;
}
__device__ __forceinline__ float warp_max(float v) {
    #pragma unroll
    for (int o = 16; o > 0; o >>= 1) v = fmaxf(v, __shfl_xor_sync(0xffffffffu, v, o));
    return v;
}

// ------------- warp-per-row softmax: combine rel-pos biases + mask (f16 in place) -----------
// grid (SEQ/8, ZBAT), block 256 (8 warps, one q-row each)
__global__ void combine_softmax(__half* __restrict__ s1, const __half* __restrict__ c2p,
                                const __half* __restrict__ p2c, const int* __restrict__ amask)
{
    const int warp = threadIdx.x >> 5, lane = threadIdx.x & 31;
    const int q = blockIdx.x * 8 + warp;
    const int z = blockIdx.y, b = z >> 3;
    const float inv_scale = 0.05892556509887896f;   // 1/sqrt(288)
    __half* srow = s1 + ((size_t)z * SEQ + q) * SEQ;
    const __half* crow = c2p + ((size_t)z * SEQ + q) * PPOS;
    const __half* pz   = p2c + (size_t)z * SEQ * PPOS;
    const int mq = amask[b * SEQ + q];

    float vals[16];
    #pragma unroll
    for (int i = 0; i < 16; i++) {
        int k = lane + 32 * i;
        int d = q - k + SPAN;
        float s = (__half2float(srow[k]) + __half2float(crow[d])
                 + __half2float(pz[(size_t)k * PPOS + d])) * inv_scale;
        int mk = amask[b * SEQ + k];
        vals[i] = (mq * mk > 0) ? s : NEGF;
    }
    float mx = vals[0];
    #pragma unroll
    for (int i = 1; i < 16; i++) mx = fmaxf(mx, vals[i]);
    mx = warp_max(mx);
    float sum = 0.f;
    #pragma unroll
    for (int i = 0; i < 16; i++) { vals[i] = __expf(vals[i] - mx); sum += vals[i]; }
    float inv = 1.0f / warp_sum(sum);
    #pragma unroll
    for (int i = 0; i < 16; i++) srow[lane + 32 * i] = __float2half(vals[i] * inv);
}

// ---------------- LayerNorm: warp-per-row ----------------
// grid NTOK/8, block 256 (8 warps, one token each). 24 elems/lane.
__global__ void add_ln(const __half* __restrict__ a, const float* __restrict__ res,
                       const float* __restrict__ g, const float* __restrict__ beta,
                       float* __restrict__ outF, __half* __restrict__ outH)
{
    const int warp = threadIdx.x >> 5, lane = threadIdx.x & 31;
    const int row = blockIdx.x * 8 + warp;
    const __half* ar = a + (size_t)row * DMODEL;
    const float*  rr = res + (size_t)row * DMODEL;
    float v[24];
    float partial = 0.f;
    #pragma unroll
    for (int i = 0; i < 6; i++) {
        int j = lane * 4 + i * 128;
        uint2 hu = *reinterpret_cast<const uint2*>(ar + j);
        __half2 h0 = *reinterpret_cast<__half2*>(&hu.x);
        __half2 h1 = *reinterpret_cast<__half2*>(&hu.y);
        float4 rv = *reinterpret_cast<const float4*>(rr + j);
        v[4*i+0] = __half2float(h0.x) + rv.x;
        v[4*i+1] = __half2float(h0.y) + rv.y;
        v[4*i+2] = __half2float(h1.x) + rv.z;
        v[4*i+3] = __half2float(h1.y) + rv.w;
        partial += v[4*i+0] + v[4*i+1] + v[4*i+2] + v[4*i+3];
    }
    float mean = warp_sum(partial) * (1.0f / DMODEL);
    float p2 = 0.f;
    #pragma unroll
    for (int i = 0; i < 24; i++) { float d = v[i] - mean; p2 += d * d; }
    float rstd = rsqrtf(warp_sum(p2) * (1.0f / DMODEL) + LN_EPS);
    float* oF = outF + (size_t)row * DMODEL;
    __half* oH = outH + (size_t)row * DMODEL;
    #pragma unroll
    for (int i = 0; i < 6; i++) {
        int j = lane * 4 + i * 128;
        float4 o;
        o.x = (v[4*i+0] - mean) * rstd * g[j]   + beta[j];
        o.y = (v[4*i+1] - mean) * rstd * g[j+1] + beta[j+1];
        o.z = (v[4*i+2] - mean) * rstd * g[j+2] + beta[j+2];
        o.w = (v[4*i+3] - mean) * rstd * g[j+3] + beta[j+3];
        *reinterpret_cast<float4*>(oF + j) = o;
        __half2 h0 = __floats2half2_rn(o.x, o.y), h1 = __floats2half2_rn(o.z, o.w);
        uint2 hu;
        hu.x = *reinterpret_cast<uint32_t*>(&h0);
        hu.y = *reinterpret_cast<uint32_t*>(&h1);
        *reinterpret_cast<uint2*>(oH + j) = hu;
    }
}

__global__ void embed_ln(const float* __restrict__ x, const float* __restrict__ pos,
                         const float* __restrict__ g, const float* __restrict__ beta,
                         const int* __restrict__ amask, float* __restrict__ outF,
                         __half* __restrict__ outH)
{
    const int warp = threadIdx.x >> 5, lane = threadIdx.x & 31;
    const int row = blockIdx.x * 8 + warp;
    const int s = row & (SEQ - 1);
    const float* xr = x + (size_t)row * DMODEL;
    const float* pr = pos + (size_t)s * DMODEL;
    float v[24];
    float partial = 0.f;
    #pragma unroll
    for (int i = 0; i < 6; i++) {
        int j = lane * 4 + i * 128;
        float4 xv = *reinterpret_cast<const float4*>(xr + j);
        float4 pv = *reinterpret_cast<const float4*>(pr + j);
        v[4*i+0] = xv.x + pv.x; v[4*i+1] = xv.y + pv.y;
        v[4*i+2] = xv.z + pv.z; v[4*i+3] = xv.w + pv.w;
        partial += v[4*i+0] + v[4*i+1] + v[4*i+2] + v[4*i+3];
    }
    float mean = warp_sum(partial) * (1.0f / DMODEL);
    float p2 = 0.f;
    #pragma unroll
    for (int i = 0; i < 24; i++) { float d = v[i] - mean; p2 += d * d; }
    float rstd = rsqrtf(warp_sum(p2) * (1.0f / DMODEL) + LN_EPS);
    float mf = (float)amask[row];
    float* oF = outF + (size_t)row * DMODEL;
    __half* oH = outH + (size_t)row * DMODEL;
    #pragma unroll
    for (int i = 0; i < 6; i++) {
        int j = lane * 4 + i * 128;
        float4 o;
        o.x = ((v[4*i+0] - mean) * rstd * g[j]   + beta[j])   * mf;
        o.y = ((v[4*i+1] - mean) * rstd * g[j+1] + beta[j+1]) * mf;
        o.z = ((v[4*i+2] - mean) * rstd * g[j+2] + beta[j+2]) * mf;
        o.w = ((v[4*i+3] - mean) * rstd * g[j+3] + beta[j+3]) * mf;
        *reinterpret_cast<float4*>(oF + j) = o;
        __half2 h0 = __floats2half2_rn(o.x, o.y), h1 = __floats2half2_rn(o.z, o.w);
        uint2 hu;
        hu.x = *reinterpret_cast<uint32_t*>(&h0);
        hu.y = *reinterpret_cast<uint32_t*>(&h1);
        *reinterpret_cast<uint2*>(oH + j) = hu;
    }
}

// ==================================== launcher ====================================
static inline int pgrid(int tiles, int cap) { return tiles < cap ? tiles : cap; }

extern "C" void kernel_launch(void* const* d_in, const int* in_sizes, int n_in,
                              void* d_out, int out_size)
{
    const float* x       = (const float*)d_in[0];
    const float* pos_emb = (const float*)d_in[1];
    const float* rel_emb = (const float*)d_in[2];
    const float* ln_e_g  = (const float*)d_in[3];
    const float* ln_e_b  = (const float*)d_in[4];
    const float* Wq  = (const float*)d_in[5];
    const float* bq  = (const float*)d_in[6];
    const float* Wk  = (const float*)d_in[7];
    const float* bk  = (const float*)d_in[8];
    const float* Wv  = (const float*)d_in[9];
    const float* bv  = (const float*)d_in[10];
    const float* Wo  = (const float*)d_in[11];
    const float* bo  = (const float*)d_in[12];
    const float* Wpk = (const float*)d_in[13];
    const float* bpk = (const float*)d_in[14];
    const float* Wpq = (const float*)d_in[15];
    const float* bpq = (const float*)d_in[16];
    const float* ln1g = (const float*)d_in[17];
    const float* ln1b = (const float*)d_in[18];
    const float* Wi   = (const float*)d_in[19];
    const float* bi   = (const float*)d_in[20];
    const float* Wo2  = (const float*)d_in[21];
    const float* bo2  = (const float*)d_in[22];
    const float* ln2g = (const float*)d_in[23];
    const float* ln2b = (const float*)d_in[24];
    const int*   amask = (const int*)d_in[25];

    float *h32, *bqkv;
    __half *h16, *qkv, *ctx, *tmp, *wqkv, *wi, *wo2, *wo, *wpk, *wpq, *rel;
    __half *pk, *pq, *s1, *c2p, *p2c, *ffn;
    cudaGetSymbolAddress((void**)&h32,  g_h32);
    cudaGetSymbolAddress((void**)&h16,  g_h16);
    cudaGetSymbolAddress((void**)&qkv,  g_qkv);
    cudaGetSymbolAddress((void**)&ctx,  g_ctx);
    cudaGetSymbolAddress((void**)&tmp,  g_tmp);
    cudaGetSymbolAddress((void**)&wqkv, g_wqkv);
    cudaGetSymbolAddress((void**)&bqkv, g_bqkv);
    cudaGetSymbolAddress((void**)&wi,   g_wi);
    cudaGetSymbolAddress((void**)&wo2,  g_wo2);
    cudaGetSymbolAddress((void**)&wo,   g_wo);
    cudaGetSymbolAddress((void**)&wpk,  g_wpk);
    cudaGetSymbolAddress((void**)&wpq,  g_wpq);
    cudaGetSymbolAddress((void**)&rel,  g_rel);
    cudaGetSymbolAddress((void**)&pk,   g_pk);
    cudaGetSymbolAddress((void**)&pq,   g_pq);
    cudaGetSymbolAddress((void**)&s1,   g_s1);
    cudaGetSymbolAddress((void**)&c2p,  g_c2p);
    cudaGetSymbolAddress((void**)&p2c,  g_p2c);
    cudaGetSymbolAddress((void**)&ffn,  g_ffn);

    const long DD = (long)DMODEL * DMODEL;
    const long S2 = (long)SEQ * SEQ;
    const long SP = (long)SEQ * PPOS;
    const long SD3 = (long)SEQ * D3;
    const long PD = (long)PPOS * DMODEL;
    const int CAP = 296;

    const int SM_NN128 = 4 * 128 * 80 + 4 * 32 * 272;   // 75776
    const int SM_NT128 = 4 * 128 * 80 + 4 * 128 * 80;   // 81920
    const int SM_NN96  = 4 * 128 * 80 + 4 * 32 * 208;   // 67584
    cudaFuncSetAttribute(hgemm<128,128,8,false>, cudaFuncAttributeMaxDynamicSharedMemorySize, SM_NN128);
    cudaFuncSetAttribute(hgemm<128,128,8,true>,  cudaFuncAttributeMaxDynamicSharedMemorySize, SM_NT128);
    cudaFuncSetAttribute(hgemm<128,96,6,false>,  cudaFuncAttributeMaxDynamicSharedMemorySize, SM_NN96);

    // ---- fused prologue (1 launch) ----
    {
        long total = (long)NLAYER*DMODEL*D3 + 2L*NLAYER*DMODEL*FF + 3L*NLAYER*DD
                   + (long)PPOS*DMODEL + (long)NLAYER*D3;
        prep_all<<<(unsigned)((total / 4 + 255) / 256), 256>>>(
            Wq, Wk, Wv, bq, bk, bv, Wi, Wo2, Wo, Wpk, Wpq, rel_emb,
            wqkv, bqkv, wi, wo2, wo, wpk, wpq, rel);
    }
    embed_ln<<<NTOK/8, 256>>>(x, pos_emb, ln_e_g, ln_e_b, amask, h32, h16);

    // pos projections, all layers (z = layer): 48 tiles/z
    hgemm<128,128,8,false><<<pgrid(288, CAP), 256, SM_NN128>>>(
        rel, wpk, bpk, pk, DMODEL, DMODEL, DMODEL, DMODEL,
        0, 0, 0, DD, DMODEL, 0, PD, 0, 288, 48, 6, 0);
    hgemm<128,128,8,false><<<pgrid(288, CAP), 256, SM_NN128>>>(
        rel, wpq, bpq, pq, DMODEL, DMODEL, DMODEL, DMODEL,
        0, 0, 0, DD, DMODEL, 0, PD, 0, 288, 48, 6, 0);

    for (int l = 0; l < NLAYER; l++) {
        // fused QKV: 576 tiles
        hgemm<128,128,8,false><<<pgrid(576, CAP), 256, SM_NN128>>>(
            h16, wqkv + (size_t)l * DMODEL * D3, bqkv + (size_t)l * D3, qkv,
            DMODEL, DMODEL, D3, D3, 0,0,0,0,0, 0,0, 0, 576, 576, 18, 0);

        // scores = Q @ K^T
        hgemm<128,128,8,true><<<pgrid(1024, CAP), 256, SM_NT128>>>(
            qkv, qkv + DMODEL, nullptr, s1, DH, D3, D3, SEQ,
            SD3, DH, SD3, DH, 0, 8*S2, S2, 0, 1024, 16, 4, 0);
        // c2p = Q @ PK^T (banded)
        hgemm<128,128,8,true><<<pgrid(1280, CAP), 256, SM_NT128>>>(
            qkv, pk + (size_t)l * PD, nullptr, c2p, DH, D3, DMODEL, PPOS,
            SD3, DH, 0, DH, 0, 8*SP, SP, 0, 1280, 20, 0, 1);
        // p2c = K @ PQ^T (banded)
        hgemm<128,128,8,true><<<pgrid(1280, CAP), 256, SM_NT128>>>(
            qkv + DMODEL, pq + (size_t)l * PD, nullptr, p2c, DH, D3, DMODEL, PPOS,
            SD3, DH, 0, DH, 0, 8*SP, SP, 0, 1280, 20, 0, 2);

        combine_softmax<<<dim3(SEQ/8, ZBAT), 256>>>(s1, c2p, p2c, amask);

        // ctx = probs @ V -> [b, q, h*96+d]
        hgemm<128,96,6,false><<<pgrid(256, CAP), 192, SM_NN96>>>(
            s1, qkv + 2*DMODEL, nullptr, ctx, SEQ, SEQ, D3, DMODEL,
            8*S2, S2, SD3, DH, 0, (long)SEQ*DMODEL, DH, 0, 256, 4, 1, 0);

        // attn out proj: 192 tiles
        hgemm<128,128,8,false><<<pgrid(192, CAP), 256, SM_NN128>>>(
            ctx, wo + (size_t)l*DD, bo + (size_t)l*DMODEL, tmp,
            DMODEL, DMODEL, DMODEL, DMODEL, 0,0,0,0,0, 0,0, 0, 192, 192, 6, 0);
        add_ln<<<NTOK/8, 256>>>(tmp, h32, ln1g + (size_t)l*DMODEL, ln1b + (size_t)l*DMODEL, h32, h16);

        // FFN1 (gelu): 768 tiles
        hgemm<128,128,8,false><<<pgrid(768, CAP), 256, SM_NN128>>>(
            h16, wi + (size_t)l*DMODEL*FF, bi + (size_t)l*FF, ffn,
            DMODEL, DMODEL, FF, FF, 0,0,0,0,0, 0,0, 1, 768, 768, 24, 0);
        // FFN2: K=3072, 192 tiles
        hgemm<128,128,8,false><<<pgrid(192, CAP), 256, SM_NN128>>>(
            ffn, wo2 + (size_t)l*FF*DMODEL, bo2 + (size_t)l*DMODEL, tmp,
            FF, FF, DMODEL, DMODEL, 0,0,0,0,0, 0,0, 0, 192, 192, 6, 0);

        float* outF = (l == NLAYER - 1) ? (float*)d_out : h32;
        add_ln<<<NTOK/8, 256>>>(tmp, h32, ln2g + (size_t)l*DMODEL, ln2b + (size_t)l*DMODEL, outF, h16);
    }
}

// round 15
// speedup vs baseline: 1.2432x; 1.0512x over previous
#include <cuda_runtime.h>
#include <cuda_fp16.h>
#include <math.h>
#include <stdint.h>

#define DMODEL 768
#define NH     8
#define DH     96
#define NLAYER 6
#define SPAN   512
#define SEQ    512
#define BATCH  8
#define PPOS   1024
#define FF     3072
#define NTOK   (BATCH*SEQ)
#define ZBAT   (BATCH*NH)
#define LN_EPS 1e-7f
#define NEGF   (-3.402823466e38f)
#define D3     (3*DMODEL)

// -------------------- scratch --------------------
__device__ float  g_h32 [NTOK*DMODEL];
__device__ __half g_h16 [NTOK*DMODEL];
__device__ __half g_qkv [(size_t)NTOK*D3];
__device__ __half g_ctx [NTOK*DMODEL];
__device__ __half g_tmp [NTOK*DMODEL];
__device__ __half g_wqkv[(size_t)NLAYER*DMODEL*D3];
__device__ float  g_bqkv[NLAYER*D3];
__device__ __half g_wi  [(size_t)NLAYER*DMODEL*FF];
__device__ __half g_wo2 [(size_t)NLAYER*FF*DMODEL];
__device__ __half g_wo  [(size_t)NLAYER*DMODEL*DMODEL];
__device__ __half g_wpk [(size_t)NLAYER*DMODEL*DMODEL];
__device__ __half g_wpq [(size_t)NLAYER*DMODEL*DMODEL];
__device__ __half g_rel [PPOS*DMODEL];
__device__ __half g_pk  [(size_t)NLAYER*PPOS*DMODEL];
__device__ __half g_pq  [(size_t)NLAYER*PPOS*DMODEL];
__device__ __half g_s1  [(size_t)ZBAT*SEQ*SEQ];
__device__ __half g_c2p [(size_t)ZBAT*SEQ*PPOS];
__device__ __half g_p2c [(size_t)ZBAT*SEQ*PPOS];
__device__ __half g_ffn [(size_t)NTOK*FF];

// -------------------- helpers --------------------
__device__ __forceinline__ float gelu_f(float x) {
    return 0.5f * x * (1.0f + erff(x * 0.7071067811865475f));
}
__device__ __forceinline__ uint32_t smem_u32(const void* p) {
    uint32_t a;
    asm("{ .reg .u64 t; cvta.to.shared.u64 t, %1; cvt.u32.u64 %0, t; }" : "=r"(a) : "l"(p));
    return a;
}
__device__ __forceinline__ void mma_f16(float c[4], const uint32_t a[4], const uint32_t b[2]) {
    asm volatile(
        "mma.sync.aligned.m16n8k16.row.col.f32.f16.f16.f32 "
        "{%0,%1,%2,%3},{%4,%5,%6,%7},{%8,%9},{%0,%1,%2,%3};\n"
        : "+f"(c[0]), "+f"(c[1]), "+f"(c[2]), "+f"(c[3])
        : "r"(a[0]), "r"(a[1]), "r"(a[2]), "r"(a[3]), "r"(b[0]), "r"(b[1]));
}
__device__ __forceinline__ void ldsm_x4(uint32_t r[4], uint32_t addr) {
    asm volatile("ldmatrix.sync.aligned.m8n8.x4.shared.b16 {%0,%1,%2,%3}, [%4];"
        : "=r"(r[0]), "=r"(r[1]), "=r"(r[2]), "=r"(r[3]) : "r"(addr));
}
__device__ __forceinline__ void ldsm_x4t(uint32_t r[4], uint32_t addr) {
    asm volatile("ldmatrix.sync.aligned.m8n8.x4.trans.shared.b16 {%0,%1,%2,%3}, [%4];"
        : "=r"(r[0]), "=r"(r[1]), "=r"(r[2]), "=r"(r[3]) : "r"(addr));
}
__device__ __forceinline__ void cp16(uint32_t dst, const void* src) {
    asm volatile("cp.async.cg.shared.global [%0], [%1], 16;" :: "r"(dst), "l"(src));
}
#define CP_COMMIT() asm volatile("cp.async.commit_group;" ::: "memory")
#define CP_WAIT2()  asm volatile("cp.async.wait_group 2;" ::: "memory")

// ============================ cp.async FP16 mma GEMM (Round-10 proven) ============================
template<int BM, int BN, int NWARP, bool BT>
__global__ void __launch_bounds__(NWARP*32, 512/(NWARP*32))
hgemm(const __half* __restrict__ A, const __half* __restrict__ B,
      const float* __restrict__ bias, __half* __restrict__ C,
      int K, int lda, int ldb, int ldc,
      long sAb, long sAh, long sBb, long sBh, long sBiasH,
      long sCb, long sCh, int act, int ntiles, int tpz, int tiles_x, int band)
{
    constexpr int THREADS = NWARP * 32;
    constexpr int WM = 64, WN = 32;
    constexpr int MI = WM / 16, NI = WN / 8;
    constexpr int WARPS_N = BN / WN;
    constexpr int ROWA = 80;
    constexpr int ASTG = BM * ROWA;
    constexpr int ROWB = BT ? 80 : (BN + 8) * 2;
    constexpr int BSTG = BT ? (BN * 80) : (32 * ROWB);
    constexpr int ACH  = BM * 4;
    constexpr int A_IT = (ACH + THREADS - 1) / THREADS;
    constexpr int BCHN = BN / 8;
    constexpr int BCH  = BT ? (BN * 4) : (32 * BCHN);
    constexpr int B_IT = (BCH + THREADS - 1) / THREADS;

    extern __shared__ char sm[];
    const uint32_t asb = smem_u32(sm);
    const uint32_t bsb = asb + 4 * ASTG;

    const int tid = threadIdx.x;
    const int wid = tid >> 5, lane = tid & 31;
    const int g = lane >> 2, tig = lane & 3;
    const int wm0 = (wid / WARPS_N) * WM, wn0 = (wid % WARPS_N) * WN;
    const int nk = K / 32;
    const long bAdv = BT ? 32 : (long)32 * ldb;

    const uint32_t aoff = (uint32_t)(lane & 15) * ROWA + (uint32_t)(lane >> 4) * 16;
    const uint32_t boffT = ((uint32_t)(lane & 7) + (uint32_t)((lane >> 4) & 1) * 8) * 80
                         + (uint32_t)((lane >> 3) & 1) * 16;
    const uint32_t boffN = ((uint32_t)(lane & 7) + (uint32_t)((lane >> 3) & 1) * 8) * ROWB
                         + (uint32_t)((lane >> 4) & 1) * 16;

    for (int T = blockIdx.x; T < ntiles; T += gridDim.x) {
        const int z = T / tpz, tl = T - z * tpz;
        int ty, tx;
        if (band == 0) { ty = tl / tiles_x; tx = tl - ty * tiles_x; }
        else { ty = tl / 5; int rr = tl - ty * 5; tx = (band == 1 ? ty : 3 - ty) + rr; }
        const int m0 = ty * BM, n0 = tx * BN;
        const int bb = z >> 3, hh = z & 7;
        const __half* Az = A + (size_t)bb * sAb + (size_t)hh * sAh;
        const __half* Bz = B + (size_t)bb * sBb + (size_t)hh * sBh;
        __half* Cz = C + (size_t)bb * sCb + (size_t)hh * sCh;
        const float* biasp = bias ? (bias + (size_t)hh * sBiasH) : nullptr;

        const __half* aS[A_IT]; uint32_t aD[A_IT];
        #pragma unroll
        for (int i = 0; i < A_IT; i++) {
            int lin = tid + i * THREADS;
            if ((ACH % THREADS == 0) || lin < ACH) {
                int r = lin >> 2, c = lin & 3;
                aS[i] = Az + (size_t)(m0 + r) * lda + c * 8;
                aD[i] = (uint32_t)r * ROWA + (uint32_t)c * 16;
            }
        }
        const __half* bS[B_IT]; uint32_t bD[B_IT];
        #pragma unroll
        for (int i = 0; i < B_IT; i++) {
            int lin = tid + i * THREADS;
            if ((BCH % THREADS == 0) || lin < BCH) {
                if (BT) {
                    int r = lin >> 2, c = lin & 3;
                    bS[i] = Bz + (size_t)(n0 + r) * ldb + c * 8;
                    bD[i] = (uint32_t)r * 80 + (uint32_t)c * 16;
                } else {
                    int kk = lin / BCHN, c = lin - kk * BCHN;
                    bS[i] = Bz + (size_t)kk * ldb + n0 + c * 8;
                    bD[i] = (uint32_t)kk * ROWB + (uint32_t)c * 16;
                }
            }
        }

        float acc[MI][NI][4];
        #pragma unroll
        for (int i = 0; i < MI; i++)
            #pragma unroll
            for (int j = 0; j < NI; j++)
                #pragma unroll
                for (int t = 0; t < 4; t++) acc[i][j][t] = 0.f;

        auto issue = [&](int s) {
            if (s < nk) {
                const uint32_t ab = asb + (s & 3) * ASTG;
                const uint32_t bbm = bsb + (s & 3) * BSTG;
                #pragma unroll
                for (int i = 0; i < A_IT; i++) {
                    int lin = tid + i * THREADS;
                    if ((ACH % THREADS == 0) || lin < ACH) {
                        cp16(ab + aD[i], aS[i]);
                        aS[i] += 32;
                    }
                }
                #pragma unroll
                for (int i = 0; i < B_IT; i++) {
                    int lin = tid + i * THREADS;
                    if ((BCH % THREADS == 0) || lin < BCH) {
                        cp16(bbm + bD[i], bS[i]);
                        bS[i] += bAdv;
                    }
                }
            }
            CP_COMMIT();
        };

        __syncthreads();
        issue(0); issue(1); issue(2);
        int fetch = 3;

        uint32_t aStg[4], bStg[4];
        #pragma unroll
        for (int b4 = 0; b4 < 4; b4++) {
            aStg[b4] = asb + (uint32_t)b4 * ASTG + (uint32_t)wm0 * ROWA + aoff;
            bStg[b4] = BT ? (bsb + (uint32_t)b4 * BSTG + (uint32_t)wn0 * 80 + boffT)
                          : (bsb + (uint32_t)b4 * BSTG + boffN + (uint32_t)wn0 * 2);
        }

        for (int it = 0; it < nk; it++) {
            CP_WAIT2();
            __syncthreads();
            issue(fetch); fetch++;
            const int buf = it & 3;
            const uint32_t aB = aStg[buf];
            const uint32_t bB = bStg[buf];
            #pragma unroll
            for (int ks = 0; ks < 2; ks++) {
                uint32_t af[MI][4], bf[NI][2];
                #pragma unroll
                for (int i = 0; i < MI; i++)
                    ldsm_x4(af[i], aB + (uint32_t)i * (16 * ROWA) + (uint32_t)ks * 32);
                if (BT) {
                    #pragma unroll
                    for (int jj = 0; jj < NI / 2; jj++) {
                        uint32_t t4[4];
                        ldsm_x4(t4, bB + (uint32_t)ks * 32 + (uint32_t)jj * (16 * 80));
                        bf[2 * jj][0] = t4[0]; bf[2 * jj][1] = t4[1];
                        bf[2 * jj + 1][0] = t4[2]; bf[2 * jj + 1][1] = t4[3];
                    }
                } else {
                    #pragma unroll
                    for (int jj = 0; jj < NI / 2; jj++) {
                        uint32_t t4[4];
                        ldsm_x4t(t4, bB + (uint32_t)(ks * 16) * ROWB + (uint32_t)jj * 32);
                        bf[2 * jj][0] = t4[0]; bf[2 * jj][1] = t4[1];
                        bf[2 * jj + 1][0] = t4[2]; bf[2 * jj + 1][1] = t4[3];
                    }
                }
                #pragma unroll
                for (int i = 0; i < MI; i++)
                    #pragma unroll
                    for (int j = 0; j < NI; j++)
                        mma_f16(acc[i][j], af[i], bf[j]);
            }
        }

        // epilogue -> f16
        #pragma unroll
        for (int i = 0; i < MI; i++) {
            int r0 = m0 + wm0 + 16 * i + g;
            #pragma unroll
            for (int j = 0; j < NI; j++) {
                int col = n0 + wn0 + 8 * j + 2 * tig;
                float b0v = biasp ? biasp[col] : 0.f;
                float b1v = biasp ? biasp[col + 1] : 0.f;
                float v0 = acc[i][j][0] + b0v, v1 = acc[i][j][1] + b1v;
                float v2 = acc[i][j][2] + b0v, v3 = acc[i][j][3] + b1v;
                if (act == 1) { v0 = gelu_f(v0); v1 = gelu_f(v1); v2 = gelu_f(v2); v3 = gelu_f(v3); }
                *reinterpret_cast<__half2*>(Cz + (size_t)r0 * ldc + col) = __floats2half2_rn(v0, v1);
                *reinterpret_cast<__half2*>(Cz + (size_t)(r0 + 8) * ldc + col) = __floats2half2_rn(v2, v3);
            }
        }
    }
}

// -------------------- fused prologue: ONE launch for all weight prep --------------------
__global__ void prep_all(const float* __restrict__ Wq, const float* __restrict__ Wk,
                         const float* __restrict__ Wv, const float* __restrict__ bq,
                         const float* __restrict__ bk, const float* __restrict__ bv,
                         const float* __restrict__ Wi, const float* __restrict__ Wo2,
                         const float* __restrict__ Wo, const float* __restrict__ Wpk,
                         const float* __restrict__ Wpq, const float* __restrict__ rel_emb,
                         __half* __restrict__ wqkv, float* __restrict__ bqkv,
                         __half* __restrict__ wi, __half* __restrict__ wo2,
                         __half* __restrict__ wo, __half* __restrict__ wpk,
                         __half* __restrict__ wpq, __half* __restrict__ rel)
{
    const long N1 = (long)NLAYER * DMODEL * D3;
    const long N2 = (long)NLAYER * DMODEL * FF;
    const long N4 = (long)NLAYER * DMODEL * DMODEL;
    const long N7 = (long)PPOS * DMODEL;
    const long N8 = (long)NLAYER * D3;
    long e = ((long)blockIdx.x * blockDim.x + threadIdx.x) * 4;
    const float* src; __half* dst; long i;
    if (e < N1) {
        i = e;
        int l = (int)(i / ((long)DMODEL * D3));
        long r = i - (long)l * DMODEL * D3;
        int row = (int)(r / D3), col = (int)(r - (long)row * D3);
        const float* s2; int c;
        if (col < DMODEL)        { s2 = Wq; c = col; }
        else if (col < 2*DMODEL) { s2 = Wk; c = col - DMODEL; }
        else                     { s2 = Wv; c = col - 2*DMODEL; }
        float4 v = *reinterpret_cast<const float4*>(s2 + ((size_t)l * DMODEL + row) * DMODEL + c);
        wqkv[i] = __float2half(v.x); wqkv[i+1] = __float2half(v.y);
        wqkv[i+2] = __float2half(v.z); wqkv[i+3] = __float2half(v.w);
        return;
    }
    e -= N1;
    if (e < N2)      { src = Wi;  dst = wi;  i = e; }
    else if ((e -= N2) < N2) { src = Wo2; dst = wo2; i = e; }
    else if ((e -= N2) < N4) { src = Wo;  dst = wo;  i = e; }
    else if ((e -= N4) < N4) { src = Wpk; dst = wpk; i = e; }
    else if ((e -= N4) < N4) { src = Wpq; dst = wpq; i = e; }
    else if ((e -= N4) < N7) { src = rel_emb; dst = rel; i = e; }
    else {
        e -= N7;
        if (e < N8) {
            #pragma unroll
            for (int t = 0; t < 4; t++) {
                long idx = e + t;
                int l = (int)(idx / D3), col = (int)(idx - (long)l * D3);
                const float* s2; int c;
                if (col < DMODEL)        { s2 = bq; c = col; }
                else if (col < 2*DMODEL) { s2 = bk; c = col - DMODEL; }
                else                     { s2 = bv; c = col - 2*DMODEL; }
                bqkv[idx] = s2[(size_t)l * DMODEL + c];
            }
        }
        return;
    }
    float4 v = *reinterpret_cast<const float4*>(src + i);
    dst[i] = __float2half(v.x); dst[i+1] = __float2half(v.y);
    dst[i+2] = __float2half(v.z); dst[i+3] = __float2half(v.w);
}

// -------------------- warp reductions --------------------
__device__ __forceinline__ float warp_sum(float v) {
    #pragma unroll
    for (int o = 16; o > 0; o >>= 1) v += __shfl_xor_sync(0xffffffffu, v, o);
    return v;
}
__device__ __forceinline__ float warp_max(float v) {
    #pragma unroll
    for (int o = 16; o > 0; o >>= 1) v = fmaxf(v, __shfl_xor_sync(0xffffffffu, v, o));
    return v;
}

// ------------- warp-per-row softmax -----------
__global__ void combine_softmax(__half* __restrict__ s1, const __half* __restrict__ c2p,
                                const __half* __restrict__ p2c, const int* __restrict__ amask)
{
    const int warp = threadIdx.x >> 5, lane = threadIdx.x & 31;
    const int q = blockIdx.x * 8 + warp;
    const int z = blockIdx.y, b = z >> 3;
    const float inv_scale = 0.05892556509887896f;   // 1/sqrt(288)
    __half* srow = s1 + ((size_t)z * SEQ + q) * SEQ;
    const __half* crow = c2p + ((size_t)z * SEQ + q) * PPOS;
    const __half* pz   = p2c + (size_t)z * SEQ * PPOS;
    const int mq = amask[b * SEQ + q];

    float vals[16];
    #pragma unroll
    for (int i = 0; i < 16; i++) {
        int k = lane + 32 * i;
        int d = q - k + SPAN;
        float s = (__half2float(srow[k]) + __half2float(crow[d])
                 + __half2float(pz[(size_t)k * PPOS + d])) * inv_scale;
        int mk = amask[b * SEQ + k];
        vals[i] = (mq * mk > 0) ? s : NEGF;
    }
    float mx = vals[0];
    #pragma unroll
    for (int i = 1; i < 16; i++) mx = fmaxf(mx, vals[i]);
    mx = warp_max(mx);
    float sum = 0.f;
    #pragma unroll
    for (int i = 0; i < 16; i++) { vals[i] = __expf(vals[i] - mx); sum += vals[i]; }
    float inv = 1.0f / warp_sum(sum);
    #pragma unroll
    for (int i = 0; i < 16; i++) srow[lane + 32 * i] = __float2half(vals[i] * inv);
}

// ---------------- LayerNorm: warp-per-row ----------------
__global__ void add_ln(const __half* __restrict__ a, const float* __restrict__ res,
                       const float* __restrict__ g, const float* __restrict__ beta,
                       float* __restrict__ outF, __half* __restrict__ outH)
{
    const int warp = threadIdx.x >> 5, lane = threadIdx.x & 31;
    const int row = blockIdx.x * 8 + warp;
    const __half* ar = a + (size_t)row * DMODEL;
    const float*  rr = res + (size_t)row * DMODEL;
    float v[24];
    float partial = 0.f;
    #pragma unroll
    for (int i = 0; i < 6; i++) {
        int j = lane * 4 + i * 128;
        uint2 hu = *reinterpret_cast<const uint2*>(ar + j);
        __half2 h0 = *reinterpret_cast<__half2*>(&hu.x);
        __half2 h1 = *reinterpret_cast<__half2*>(&hu.y);
        float4 rv = *reinterpret_cast<const float4*>(rr + j);
        v[4*i+0] = __half2float(h0.x) + rv.x;
        v[4*i+1] = __half2float(h0.y) + rv.y;
        v[4*i+2] = __half2float(h1.x) + rv.z;
        v[4*i+3] = __half2float(h1.y) + rv.w;
        partial += v[4*i+0] + v[4*i+1] + v[4*i+2] + v[4*i+3];
    }
    float mean = warp_sum(partial) * (1.0f / DMODEL);
    float p2 = 0.f;
    #pragma unroll
    for (int i = 0; i < 24; i++) { float d = v[i] - mean; p2 += d * d; }
    float rstd = rsqrtf(warp_sum(p2) * (1.0f / DMODEL) + LN_EPS);
    float* oF = outF + (size_t)row * DMODEL;
    __half* oH = outH + (size_t)row * DMODEL;
    #pragma unroll
    for (int i = 0; i < 6; i++) {
        int j = lane * 4 + i * 128;
        float4 o;
        o.x = (v[4*i+0] - mean) * rstd * g[j]   + beta[j];
        o.y = (v[4*i+1] - mean) * rstd * g[j+1] + beta[j+1];
        o.z = (v[4*i+2] - mean) * rstd * g[j+2] + beta[j+2];
        o.w = (v[4*i+3] - mean) * rstd * g[j+3] + beta[j+3];
        *reinterpret_cast<float4*>(oF + j) = o;
        __half2 h0 = __floats2half2_rn(o.x, o.y), h1 = __floats2half2_rn(o.z, o.w);
        uint2 hu;
        hu.x = *reinterpret_cast<uint32_t*>(&h0);
        hu.y = *reinterpret_cast<uint32_t*>(&h1);
        *reinterpret_cast<uint2*>(oH + j) = hu;
    }
}

__global__ void embed_ln(const float* __restrict__ x, const float* __restrict__ pos,
                         const float* __restrict__ g, const float* __restrict__ beta,
                         const int* __restrict__ amask, float* __restrict__ outF,
                         __half* __restrict__ outH)
{
    const int warp = threadIdx.x >> 5, lane = threadIdx.x & 31;
    const int row = blockIdx.x * 8 + warp;
    const int s = row & (SEQ - 1);
    const float* xr = x + (size_t)row * DMODEL;
    const float* pr = pos + (size_t)s * DMODEL;
    float v[24];
    float partial = 0.f;
    #pragma unroll
    for (int i = 0; i < 6; i++) {
        int j = lane * 4 + i * 128;
        float4 xv = *reinterpret_cast<const float4*>(xr + j);
        float4 pv = *reinterpret_cast<const float4*>(pr + j);
        v[4*i+0] = xv.x + pv.x; v[4*i+1] = xv.y + pv.y;
        v[4*i+2] = xv.z + pv.z; v[4*i+3] = xv.w + pv.w;
        partial += v[4*i+0] + v[4*i+1] + v[4*i+2] + v[4*i+3];
    }
    float mean = warp_sum(partial) * (1.0f / DMODEL);
    float p2 = 0.f;
    #pragma unroll
    for (int i = 0; i < 24; i++) { float d = v[i] - mean; p2 += d * d; }
    float rstd = rsqrtf(warp_sum(p2) * (1.0f / DMODEL) + LN_EPS);
    float mf = (float)amask[row];
    float* oF = outF + (size_t)row * DMODEL;
    __half* oH = outH + (size_t)row * DMODEL;
    #pragma unroll
    for (int i = 0; i < 6; i++) {
        int j = lane * 4 + i * 128;
        float4 o;
        o.x = ((v[4*i+0] - mean) * rstd * g[j]   + beta[j])   * mf;
        o.y = ((v[4*i+1] - mean) * rstd * g[j+1] + beta[j+1]) * mf;
        o.z = ((v[4*i+2] - mean) * rstd * g[j+2] + beta[j+2]) * mf;
        o.w = ((v[4*i+3] - mean) * rstd * g[j+3] + beta[j+3]) * mf;
        *reinterpret_cast<float4*>(oF + j) = o;
        __half2 h0 = __floats2half2_rn(o.x, o.y), h1 = __floats2half2_rn(o.z, o.w);
        uint2 hu;
        hu.x = *reinterpret_cast<uint32_t*>(&h0);
        hu.y = *reinterpret_cast<uint32_t*>(&h1);
        *reinterpret_cast<uint2*>(oH + j) = hu;
    }
}

// ==================================== launcher ====================================
static inline int pgrid(int tiles, int cap) { return tiles < cap ? tiles : cap; }

extern "C" void kernel_launch(void* const* d_in, const int* in_sizes, int n_in,
                              void* d_out, int out_size)
{
    const float* x       = (const float*)d_in[0];
    const float* pos_emb = (const float*)d_in[1];
    const float* rel_emb = (const float*)d_in[2];
    const float* ln_e_g  = (const float*)d_in[3];
    const float* ln_e_b  = (const float*)d_in[4];
    const float* Wq  = (const float*)d_in[5];
    const float* bq  = (const float*)d_in[6];
    const float* Wk  = (const float*)d_in[7];
    const float* bk  = (const float*)d_in[8];
    const float* Wv  = (const float*)d_in[9];
    const float* bv  = (const float*)d_in[10];
    const float* Wo  = (const float*)d_in[11];
    const float* bo  = (const float*)d_in[12];
    const float* Wpk = (const float*)d_in[13];
    const float* bpk = (const float*)d_in[14];
    const float* Wpq = (const float*)d_in[15];
    const float* bpq = (const float*)d_in[16];
    const float* ln1g = (const float*)d_in[17];
    const float* ln1b = (const float*)d_in[18];
    const float* Wi   = (const float*)d_in[19];
    const float* bi   = (const float*)d_in[20];
    const float* Wo2  = (const float*)d_in[21];
    const float* bo2  = (const float*)d_in[22];
    const float* ln2g = (const float*)d_in[23];
    const float* ln2b = (const float*)d_in[24];
    const int*   amask = (const int*)d_in[25];

    float *h32, *bqkv;
    __half *h16, *qkv, *ctx, *tmp, *wqkv, *wi, *wo2, *wo, *wpk, *wpq, *rel;
    __half *pk, *pq, *s1, *c2p, *p2c, *ffn;
    cudaGetSymbolAddress((void**)&h32,  g_h32);
    cudaGetSymbolAddress((void**)&h16,  g_h16);
    cudaGetSymbolAddress((void**)&qkv,  g_qkv);
    cudaGetSymbolAddress((void**)&ctx,  g_ctx);
    cudaGetSymbolAddress((void**)&tmp,  g_tmp);
    cudaGetSymbolAddress((void**)&wqkv, g_wqkv);
    cudaGetSymbolAddress((void**)&bqkv, g_bqkv);
    cudaGetSymbolAddress((void**)&wi,   g_wi);
    cudaGetSymbolAddress((void**)&wo2,  g_wo2);
    cudaGetSymbolAddress((void**)&wo,   g_wo);
    cudaGetSymbolAddress((void**)&wpk,  g_wpk);
    cudaGetSymbolAddress((void**)&wpq,  g_wpq);
    cudaGetSymbolAddress((void**)&rel,  g_rel);
    cudaGetSymbolAddress((void**)&pk,   g_pk);
    cudaGetSymbolAddress((void**)&pq,   g_pq);
    cudaGetSymbolAddress((void**)&s1,   g_s1);
    cudaGetSymbolAddress((void**)&c2p,  g_c2p);
    cudaGetSymbolAddress((void**)&p2c,  g_p2c);
    cudaGetSymbolAddress((void**)&ffn,  g_ffn);

    const long DD = (long)DMODEL * DMODEL;
    const long S2 = (long)SEQ * SEQ;
    const long SP = (long)SEQ * PPOS;
    const long SD3 = (long)SEQ * D3;
    const long PD = (long)PPOS * DMODEL;
    const int CAP = 296;
    const int CAP4 = 592;

    const int SM_NN128 = 4 * 128 * 80 + 4 * 32 * 272;   // 75776
    const int SM_NT128 = 4 * 128 * 80 + 4 * 128 * 80;   // 81920
    const int SM_NN96  = 4 * 128 * 80 + 4 * 32 * 208;   // 67584
    const int SM_NN64  = 4 * 64 * 80 + 4 * 32 * 272;    // 55296
    cudaFuncSetAttribute(hgemm<128,128,8,false>, cudaFuncAttributeMaxDynamicSharedMemorySize, SM_NN128);
    cudaFuncSetAttribute(hgemm<128,128,8,true>,  cudaFuncAttributeMaxDynamicSharedMemorySize, SM_NT128);
    cudaFuncSetAttribute(hgemm<128,96,6,false>,  cudaFuncAttributeMaxDynamicSharedMemorySize, SM_NN96);
    cudaFuncSetAttribute(hgemm<64,128,4,false>,  cudaFuncAttributeMaxDynamicSharedMemorySize, SM_NN64);

    // ---- fused prologue (1 launch) ----
    {
        long total = (long)NLAYER*DMODEL*D3 + 2L*NLAYER*DMODEL*FF + 3L*NLAYER*DD
                   + (long)PPOS*DMODEL + (long)NLAYER*D3;
        prep_all<<<(unsigned)((total / 4 + 255) / 256), 256>>>(
            Wq, Wk, Wv, bq, bk, bv, Wi, Wo2, Wo, Wpk, Wpq, rel_emb,
            wqkv, bqkv, wi, wo2, wo, wpk, wpq, rel);
    }
    embed_ln<<<NTOK/8, 256>>>(x, pos_emb, ln_e_g, ln_e_b, amask, h32, h16);

    // pos projections, all layers (z = layer): 48 tiles/z
    hgemm<128,128,8,false><<<pgrid(288, CAP), 256, SM_NN128>>>(
        rel, wpk, bpk, pk, DMODEL, DMODEL, DMODEL, DMODEL,
        0, 0, 0, DD, DMODEL, 0, PD, 0, 288, 48, 6, 0);
    hgemm<128,128,8,false><<<pgrid(288, CAP), 256, SM_NN128>>>(
        rel, wpq, bpq, pq, DMODEL, DMODEL, DMODEL, DMODEL,
        0, 0, 0, DD, DMODEL, 0, PD, 0, 288, 48, 6, 0);

    for (int l = 0; l < NLAYER; l++) {
        // fused QKV: 576 tiles
        hgemm<128,128,8,false><<<pgrid(576, CAP), 256, SM_NN128>>>(
            h16, wqkv + (size_t)l * DMODEL * D3, bqkv + (size_t)l * D3, qkv,
            DMODEL, DMODEL, D3, D3, 0,0,0,0,0, 0,0, 0, 576, 576, 18, 0);

        // scores = Q @ K^T
        hgemm<128,128,8,true><<<pgrid(1024, CAP), 256, SM_NT128>>>(
            qkv, qkv + DMODEL, nullptr, s1, DH, D3, D3, SEQ,
            SD3, DH, SD3, DH, 0, 8*S2, S2, 0, 1024, 16, 4, 0);
        // c2p = Q @ PK^T (banded)
        hgemm<128,128,8,true><<<pgrid(1280, CAP), 256, SM_NT128>>>(
            qkv, pk + (size_t)l * PD, nullptr, c2p, DH, D3, DMODEL, PPOS,
            SD3, DH, 0, DH, 0, 8*SP, SP, 0, 1280, 20, 0, 1);
        // p2c = K @ PQ^T (banded)
        hgemm<128,128,8,true><<<pgrid(1280, CAP), 256, SM_NT128>>>(
            qkv + DMODEL, pq + (size_t)l * PD, nullptr, p2c, DH, D3, DMODEL, PPOS,
            SD3, DH, 0, DH, 0, 8*SP, SP, 0, 1280, 20, 0, 2);

        combine_softmax<<<dim3(SEQ/8, ZBAT), 256>>>(s1, c2p, p2c, amask);

        // ctx = probs @ V -> [b, q, h*96+d]
        hgemm<128,96,6,false><<<pgrid(256, CAP), 192, SM_NN96>>>(
            s1, qkv + 2*DMODEL, nullptr, ctx, SEQ, SEQ, D3, DMODEL,
            8*S2, S2, SD3, DH, 0, (long)SEQ*DMODEL, DH, 0, 256, 4, 1, 0);

        // attn out proj: BM=64 -> 384 tiles (full SM coverage)
        hgemm<64,128,4,false><<<pgrid(384, CAP4), 128, SM_NN64>>>(
            ctx, wo + (size_t)l*DD, bo + (size_t)l*DMODEL, tmp,
            DMODEL, DMODEL, DMODEL, DMODEL, 0,0,0,0,0, 0,0, 0, 384, 384, 6, 0);
        add_ln<<<NTOK/8, 256>>>(tmp, h32, ln1g + (size_t)l*DMODEL, ln1b + (size_t)l*DMODEL, h32, h16);

        // FFN1 (gelu): 768 tiles
        hgemm<128,128,8,false><<<pgrid(768, CAP), 256, SM_NN128>>>(
            h16, wi + (size_t)l*DMODEL*FF, bi + (size_t)l*FF, ffn,
            DMODEL, DMODEL, FF, FF, 0,0,0,0,0, 0,0, 1, 768, 768, 24, 0);
        // FFN2: K=3072, BM=64 -> 384 tiles (full SM coverage)
        hgemm<64,128,4,false><<<pgrid(384, CAP4), 128, SM_NN64>>>(
            ffn, wo2 + (size_t)l*FF*DMODEL, bo2 + (size_t)l*DMODEL, tmp,
            FF, FF, DMODEL, DMODEL, 0,0,0,0,0, 0,0, 0, 384, 384, 6, 0);

        float* outF = (l == NLAYER - 1) ? (float*)d_out : h32;
        add_ln<<<NTOK/8, 256>>>(tmp, h32, ln2g + (size_t)l*DMODEL, ln2b + (size_t)l*DMODEL, outF, h16);
    }
}

// round 16
// speedup vs baseline: 1.2604x; 1.0138x over previous
#include <cuda_runtime.h>
#include <cuda_fp16.h>
#include <math.h>
#include <stdint.h>

#define DMODEL 768
#define NH     8
#define DH     96
#define NLAYER 6
#define SPAN   512
#define SEQ    512
#define BATCH  8
#define PPOS   1024
#define FF     3072
#define NTOK   (BATCH*SEQ)
#define ZBAT   (BATCH*NH)
#define LN_EPS 1e-7f
#define NEGF   (-3.402823466e38f)
#define D3     (3*DMODEL)

// -------------------- scratch --------------------
__device__ float  g_h32 [NTOK*DMODEL];
__device__ __half g_h16 [NTOK*DMODEL];
__device__ __half g_qkv [(size_t)NTOK*D3];
__device__ __half g_ctx [NTOK*DMODEL];
__device__ __half g_tmp [NTOK*DMODEL];
__device__ __half g_wqkv[(size_t)NLAYER*DMODEL*D3];
__device__ float  g_bqkv[NLAYER*D3];
__device__ __half g_wi  [(size_t)NLAYER*DMODEL*FF];
__device__ __half g_wo2 [(size_t)NLAYER*FF*DMODEL];
__device__ __half g_wo  [(size_t)NLAYER*DMODEL*DMODEL];
__device__ __half g_wpk [(size_t)NLAYER*DMODEL*DMODEL];
__device__ __half g_wpq [(size_t)NLAYER*DMODEL*DMODEL];
__device__ __half g_rel [PPOS*DMODEL];
__device__ __half g_pk  [(size_t)NLAYER*PPOS*DMODEL];
__device__ __half g_pq  [(size_t)NLAYER*PPOS*DMODEL];
__device__ __half g_s1  [(size_t)ZBAT*SEQ*SEQ];
__device__ __half g_c2p [(size_t)ZBAT*SEQ*PPOS];
__device__ __half g_p2c [(size_t)ZBAT*SEQ*PPOS];
__device__ __half g_ffn [(size_t)NTOK*FF];

// -------------------- helpers --------------------
__device__ __forceinline__ float gelu_f(float x) {
    return 0.5f * x * (1.0f + erff(x * 0.7071067811865475f));
}
__device__ __forceinline__ uint32_t smem_u32(const void* p) {
    uint32_t a;
    asm("{ .reg .u64 t; cvta.to.shared.u64 t, %1; cvt.u32.u64 %0, t; }" : "=r"(a) : "l"(p));
    return a;
}
__device__ __forceinline__ void mma_f16(float c[4], const uint32_t a[4], const uint32_t b[2]) {
    asm volatile(
        "mma.sync.aligned.m16n8k16.row.col.f32.f16.f16.f32 "
        "{%0,%1,%2,%3},{%4,%5,%6,%7},{%8,%9},{%0,%1,%2,%3};\n"
        : "+f"(c[0]), "+f"(c[1]), "+f"(c[2]), "+f"(c[3])
        : "r"(a[0]), "r"(a[1]), "r"(a[2]), "r"(a[3]), "r"(b[0]), "r"(b[1]));
}
__device__ __forceinline__ void ldsm_x4(uint32_t r[4], uint32_t addr) {
    asm volatile("ldmatrix.sync.aligned.m8n8.x4.shared.b16 {%0,%1,%2,%3}, [%4];"
        : "=r"(r[0]), "=r"(r[1]), "=r"(r[2]), "=r"(r[3]) : "r"(addr));
}
__device__ __forceinline__ void ldsm_x4t(uint32_t r[4], uint32_t addr) {
    asm volatile("ldmatrix.sync.aligned.m8n8.x4.trans.shared.b16 {%0,%1,%2,%3}, [%4];"
        : "=r"(r[0]), "=r"(r[1]), "=r"(r[2]), "=r"(r[3]) : "r"(addr));
}
__device__ __forceinline__ void cp16(uint32_t dst, const void* src) {
    asm volatile("cp.async.cg.shared.global [%0], [%1], 16;" :: "r"(dst), "l"(src));
}
#define CP_COMMIT() asm volatile("cp.async.commit_group;" ::: "memory")
#define CP_WAIT2()  asm volatile("cp.async.wait_group 2;" ::: "memory")

// ============================ cp.async FP16 mma GEMM (Round-10 proven) ============================
template<int BM, int BN, int NWARP, bool BT>
__global__ void __launch_bounds__(NWARP*32, 512/(NWARP*32))
hgemm(const __half* __restrict__ A, const __half* __restrict__ B,
      const float* __restrict__ bias, __half* __restrict__ C,
      int K, int lda, int ldb, int ldc,
      long sAb, long sAh, long sBb, long sBh, long sBiasH,
      long sCb, long sCh, int act, int ntiles, int tpz, int tiles_x, int band)
{
    constexpr int THREADS = NWARP * 32;
    constexpr int WM = 64, WN = 32;
    constexpr int MI = WM / 16, NI = WN / 8;
    constexpr int WARPS_N = BN / WN;
    constexpr int ROWA = 80;
    constexpr int ASTG = BM * ROWA;
    constexpr int ROWB = BT ? 80 : (BN + 8) * 2;
    constexpr int BSTG = BT ? (BN * 80) : (32 * ROWB);
    constexpr int ACH  = BM * 4;
    constexpr int A_IT = (ACH + THREADS - 1) / THREADS;
    constexpr int BCHN = BN / 8;
    constexpr int BCH  = BT ? (BN * 4) : (32 * BCHN);
    constexpr int B_IT = (BCH + THREADS - 1) / THREADS;

    extern __shared__ char sm[];
    const uint32_t asb = smem_u32(sm);
    const uint32_t bsb = asb + 4 * ASTG;

    const int tid = threadIdx.x;
    const int wid = tid >> 5, lane = tid & 31;
    const int g = lane >> 2, tig = lane & 3;
    const int wm0 = (wid / WARPS_N) * WM, wn0 = (wid % WARPS_N) * WN;
    const int nk = K / 32;
    const long bAdv = BT ? 32 : (long)32 * ldb;

    const uint32_t aoff = (uint32_t)(lane & 15) * ROWA + (uint32_t)(lane >> 4) * 16;
    const uint32_t boffT = ((uint32_t)(lane & 7) + (uint32_t)((lane >> 4) & 1) * 8) * 80
                         + (uint32_t)((lane >> 3) & 1) * 16;
    const uint32_t boffN = ((uint32_t)(lane & 7) + (uint32_t)((lane >> 3) & 1) * 8) * ROWB
                         + (uint32_t)((lane >> 4) & 1) * 16;

    for (int T = blockIdx.x; T < ntiles; T += gridDim.x) {
        const int z = T / tpz, tl = T - z * tpz;
        int ty, tx;
        if (band == 0) { ty = tl / tiles_x; tx = tl - ty * tiles_x; }
        else { ty = tl / 5; int rr = tl - ty * 5; tx = (band == 1 ? ty : 3 - ty) + rr; }
        const int m0 = ty * BM, n0 = tx * BN;
        const int bb = z >> 3, hh = z & 7;
        const __half* Az = A + (size_t)bb * sAb + (size_t)hh * sAh;
        const __half* Bz = B + (size_t)bb * sBb + (size_t)hh * sBh;
        __half* Cz = C + (size_t)bb * sCb + (size_t)hh * sCh;
        const float* biasp = bias ? (bias + (size_t)hh * sBiasH) : nullptr;

        const __half* aS[A_IT]; uint32_t aD[A_IT];
        #pragma unroll
        for (int i = 0; i < A_IT; i++) {
            int lin = tid + i * THREADS;
            if ((ACH % THREADS == 0) || lin < ACH) {
                int r = lin >> 2, c = lin & 3;
                aS[i] = Az + (size_t)(m0 + r) * lda + c * 8;
                aD[i] = (uint32_t)r * ROWA + (uint32_t)c * 16;
            }
        }
        const __half* bS[B_IT]; uint32_t bD[B_IT];
        #pragma unroll
        for (int i = 0; i < B_IT; i++) {
            int lin = tid + i * THREADS;
            if ((BCH % THREADS == 0) || lin < BCH) {
                if (BT) {
                    int r = lin >> 2, c = lin & 3;
                    bS[i] = Bz + (size_t)(n0 + r) * ldb + c * 8;
                    bD[i] = (uint32_t)r * 80 + (uint32_t)c * 16;
                } else {
                    int kk = lin / BCHN, c = lin - kk * BCHN;
                    bS[i] = Bz + (size_t)kk * ldb + n0 + c * 8;
                    bD[i] = (uint32_t)kk * ROWB + (uint32_t)c * 16;
                }
            }
        }

        float acc[MI][NI][4];
        #pragma unroll
        for (int i = 0; i < MI; i++)
            #pragma unroll
            for (int j = 0; j < NI; j++)
                #pragma unroll
                for (int t = 0; t < 4; t++) acc[i][j][t] = 0.f;

        auto issue = [&](int s) {
            if (s < nk) {
                const uint32_t ab = asb + (s & 3) * ASTG;
                const uint32_t bbm = bsb + (s & 3) * BSTG;
                #pragma unroll
                for (int i = 0; i < A_IT; i++) {
                    int lin = tid + i * THREADS;
                    if ((ACH % THREADS == 0) || lin < ACH) {
                        cp16(ab + aD[i], aS[i]);
                        aS[i] += 32;
                    }
                }
                #pragma unroll
                for (int i = 0; i < B_IT; i++) {
                    int lin = tid + i * THREADS;
                    if ((BCH % THREADS == 0) || lin < BCH) {
                        cp16(bbm + bD[i], bS[i]);
                        bS[i] += bAdv;
                    }
                }
            }
            CP_COMMIT();
        };

        __syncthreads();
        issue(0); issue(1); issue(2);
        int fetch = 3;

        uint32_t aStg[4], bStg[4];
        #pragma unroll
        for (int b4 = 0; b4 < 4; b4++) {
            aStg[b4] = asb + (uint32_t)b4 * ASTG + (uint32_t)wm0 * ROWA + aoff;
            bStg[b4] = BT ? (bsb + (uint32_t)b4 * BSTG + (uint32_t)wn0 * 80 + boffT)
                          : (bsb + (uint32_t)b4 * BSTG + boffN + (uint32_t)wn0 * 2);
        }

        for (int it = 0; it < nk; it++) {
            CP_WAIT2();
            __syncthreads();
            issue(fetch); fetch++;
            const int buf = it & 3;
            const uint32_t aB = aStg[buf];
            const uint32_t bB = bStg[buf];
            #pragma unroll
            for (int ks = 0; ks < 2; ks++) {
                uint32_t af[MI][4], bf[NI][2];
                #pragma unroll
                for (int i = 0; i < MI; i++)
                    ldsm_x4(af[i], aB + (uint32_t)i * (16 * ROWA) + (uint32_t)ks * 32);
                if (BT) {
                    #pragma unroll
                    for (int jj = 0; jj < NI / 2; jj++) {
                        uint32_t t4[4];
                        ldsm_x4(t4, bB + (uint32_t)ks * 32 + (uint32_t)jj * (16 * 80));
                        bf[2 * jj][0] = t4[0]; bf[2 * jj][1] = t4[1];
                        bf[2 * jj + 1][0] = t4[2]; bf[2 * jj + 1][1] = t4[3];
                    }
                } else {
                    #pragma unroll
                    for (int jj = 0; jj < NI / 2; jj++) {
                        uint32_t t4[4];
                        ldsm_x4t(t4, bB + (uint32_t)(ks * 16) * ROWB + (uint32_t)jj * 32);
                        bf[2 * jj][0] = t4[0]; bf[2 * jj][1] = t4[1];
                        bf[2 * jj + 1][0] = t4[2]; bf[2 * jj + 1][1] = t4[3];
                    }
                }
                #pragma unroll
                for (int i = 0; i < MI; i++)
                    #pragma unroll
                    for (int j = 0; j < NI; j++)
                        mma_f16(acc[i][j], af[i], bf[j]);
            }
        }

        // epilogue -> f16
        #pragma unroll
        for (int i = 0; i < MI; i++) {
            int r0 = m0 + wm0 + 16 * i + g;
            #pragma unroll
            for (int j = 0; j < NI; j++) {
                int col = n0 + wn0 + 8 * j + 2 * tig;
                float b0v = biasp ? biasp[col] : 0.f;
                float b1v = biasp ? biasp[col + 1] : 0.f;
                float v0 = acc[i][j][0] + b0v, v1 = acc[i][j][1] + b1v;
                float v2 = acc[i][j][2] + b0v, v3 = acc[i][j][3] + b1v;
                if (act == 1) { v0 = gelu_f(v0); v1 = gelu_f(v1); v2 = gelu_f(v2); v3 = gelu_f(v3); }
                *reinterpret_cast<__half2*>(Cz + (size_t)r0 * ldc + col) = __floats2half2_rn(v0, v1);
                *reinterpret_cast<__half2*>(Cz + (size_t)(r0 + 8) * ldc + col) = __floats2half2_rn(v2, v3);
            }
        }
    }
}

// ============== merged attention trio: scores + c2p + p2c in ONE launch ==============
// 56 tiles/z: [0,16) scores (4x4), [16,36) c2p banded, [36,56) p2c banded. K=96 fixed.
__global__ void __launch_bounds__(256, 2)
hgemm_att3(const __half* __restrict__ qkv, const __half* __restrict__ pk,
           const __half* __restrict__ pq, __half* __restrict__ s1,
           __half* __restrict__ c2p, __half* __restrict__ p2c, int ntiles)
{
    constexpr int MI = 4, NI = 4;
    constexpr int ROWA = 80;
    constexpr int ASTG = 128 * ROWA;
    constexpr int BSTG = 128 * 80;
    constexpr int nk = 3;
    const long SD3 = (long)SEQ * D3;
    const long S2 = (long)SEQ * SEQ;
    const long SP = (long)SEQ * PPOS;

    extern __shared__ char sm[];
    const uint32_t asb = smem_u32(sm);
    const uint32_t bsb = asb + 4 * ASTG;

    const int tid = threadIdx.x;
    const int wid = tid >> 5, lane = tid & 31;
    const int g = lane >> 2, tig = lane & 3;
    const int wm0 = (wid >> 2) * 64, wn0 = (wid & 3) * 32;

    const uint32_t aoff = (uint32_t)(lane & 15) * ROWA + (uint32_t)(lane >> 4) * 16;
    const uint32_t boffT = ((uint32_t)(lane & 7) + (uint32_t)((lane >> 4) & 1) * 8) * 80
                         + (uint32_t)((lane >> 3) & 1) * 16;

    uint32_t aStg[4], bStg[4];
    #pragma unroll
    for (int b4 = 0; b4 < 4; b4++) {
        aStg[b4] = asb + (uint32_t)b4 * ASTG + (uint32_t)wm0 * ROWA + aoff;
        bStg[b4] = bsb + (uint32_t)b4 * BSTG + (uint32_t)wn0 * 80 + boffT;
    }

    for (int T = blockIdx.x; T < ntiles; T += gridDim.x) {
        const int z = T / 56, tl = T - z * 56;
        const int bb = z >> 3, hh = z & 7;
        const __half* Aq = qkv + (size_t)bb * SD3 + (size_t)hh * DH;
        int ty, tx, ldb, ldc;
        const __half* Az; const __half* Bz; __half* Cz;
        if (tl < 16) {
            ty = tl >> 2; tx = tl & 3;
            Az = Aq; Bz = Aq + DMODEL; ldb = D3;
            Cz = s1 + (size_t)z * S2; ldc = SEQ;
        } else if (tl < 36) {
            int L = tl - 16; ty = L / 5; tx = ty + (L - ty * 5);
            Az = Aq; Bz = pk + (size_t)hh * DH; ldb = DMODEL;
            Cz = c2p + (size_t)z * SP; ldc = PPOS;
        } else {
            int L = tl - 36; ty = L / 5; tx = (3 - ty) + (L - ty * 5);
            Az = Aq + DMODEL; Bz = pq + (size_t)hh * DH; ldb = DMODEL;
            Cz = p2c + (size_t)z * SP; ldc = PPOS;
        }
        const int m0 = ty * 128, n0 = tx * 128;

        // per-thread rolling sources (2 A-chunks, 2 B-chunks per thread)
        const __half* aS[2]; uint32_t aD[2];
        const __half* bS[2]; uint32_t bD[2];
        #pragma unroll
        for (int i = 0; i < 2; i++) {
            int lin = tid + i * 256;
            int r = lin >> 2, c = lin & 3;
            aS[i] = Az + (size_t)(m0 + r) * D3 + c * 8;
            aD[i] = (uint32_t)r * ROWA + (uint32_t)c * 16;
            bS[i] = Bz + (size_t)(n0 + r) * ldb + c * 8;
            bD[i] = (uint32_t)r * 80 + (uint32_t)c * 16;
        }

        float acc[MI][NI][4];
        #pragma unroll
        for (int i = 0; i < MI; i++)
            #pragma unroll
            for (int j = 0; j < NI; j++)
                #pragma unroll
                for (int t = 0; t < 4; t++) acc[i][j][t] = 0.f;

        auto issue = [&](int s) {
            if (s < nk) {
                const uint32_t ab = asb + s * ASTG;
                const uint32_t bbm = bsb + s * BSTG;
                #pragma unroll
                for (int i = 0; i < 2; i++) {
                    cp16(ab + aD[i], aS[i]); aS[i] += 32;
                    cp16(bbm + bD[i], bS[i]); bS[i] += 32;
                }
            }
            CP_COMMIT();
        };

        __syncthreads();
        issue(0); issue(1); issue(2);

        #pragma unroll
        for (int it = 0; it < nk; it++) {
            CP_WAIT2();
            __syncthreads();
            CP_COMMIT();                       // keep group accounting aligned
            const uint32_t aB = aStg[it];
            const uint32_t bB = bStg[it];
            #pragma unroll
            for (int ks = 0; ks < 2; ks++) {
                uint32_t af[MI][4], bf[NI][2];
                #pragma unroll
                for (int i = 0; i < MI; i++)
                    ldsm_x4(af[i], aB + (uint32_t)i * (16 * ROWA) + (uint32_t)ks * 32);
                #pragma unroll
                for (int jj = 0; jj < NI / 2; jj++) {
                    uint32_t t4[4];
                    ldsm_x4(t4, bB + (uint32_t)ks * 32 + (uint32_t)jj * (16 * 80));
                    bf[2 * jj][0] = t4[0]; bf[2 * jj][1] = t4[1];
                    bf[2 * jj + 1][0] = t4[2]; bf[2 * jj + 1][1] = t4[3];
                }
                #pragma unroll
                for (int i = 0; i < MI; i++)
                    #pragma unroll
                    for (int j = 0; j < NI; j++)
                        mma_f16(acc[i][j], af[i], bf[j]);
            }
        }

        #pragma unroll
        for (int i = 0; i < MI; i++) {
            int r0 = m0 + wm0 + 16 * i + g;
            #pragma unroll
            for (int j = 0; j < NI; j++) {
                int col = n0 + wn0 + 8 * j + 2 * tig;
                *reinterpret_cast<__half2*>(Cz + (size_t)r0 * ldc + col)
                    = __floats2half2_rn(acc[i][j][0], acc[i][j][1]);
                *reinterpret_cast<__half2*>(Cz + (size_t)(r0 + 8) * ldc + col)
                    = __floats2half2_rn(acc[i][j][2], acc[i][j][3]);
            }
        }
    }
}

// -------------------- fused prologue: ONE launch for all weight prep --------------------
__global__ void prep_all(const float* __restrict__ Wq, const float* __restrict__ Wk,
                         const float* __restrict__ Wv, const float* __restrict__ bq,
                         const float* __restrict__ bk, const float* __restrict__ bv,
                         const float* __restrict__ Wi, const float* __restrict__ Wo2,
                         const float* __restrict__ Wo, const float* __restrict__ Wpk,
                         const float* __restrict__ Wpq, const float* __restrict__ rel_emb,
                         __half* __restrict__ wqkv, float* __restrict__ bqkv,
                         __half* __restrict__ wi, __half* __restrict__ wo2,
                         __half* __restrict__ wo, __half* __restrict__ wpk,
                         __half* __restrict__ wpq, __half* __restrict__ rel)
{
    const long N1 = (long)NLAYER * DMODEL * D3;
    const long N2 = (long)NLAYER * DMODEL * FF;
    const long N4 = (long)NLAYER * DMODEL * DMODEL;
    const long N7 = (long)PPOS * DMODEL;
    const long N8 = (long)NLAYER * D3;
    long e = ((long)blockIdx.x * blockDim.x + threadIdx.x) * 4;
    const float* src; __half* dst; long i;
    if (e < N1) {
        i = e;
        int l = (int)(i / ((long)DMODEL * D3));
        long r = i - (long)l * DMODEL * D3;
        int row = (int)(r / D3), col = (int)(r - (long)row * D3);
        const float* s2; int c;
        if (col < DMODEL)        { s2 = Wq; c = col; }
        else if (col < 2*DMODEL) { s2 = Wk; c = col - DMODEL; }
        else                     { s2 = Wv; c = col - 2*DMODEL; }
        float4 v = *reinterpret_cast<const float4*>(s2 + ((size_t)l * DMODEL + row) * DMODEL + c);
        wqkv[i] = __float2half(v.x); wqkv[i+1] = __float2half(v.y);
        wqkv[i+2] = __float2half(v.z); wqkv[i+3] = __float2half(v.w);
        return;
    }
    e -= N1;
    if (e < N2)      { src = Wi;  dst = wi;  i = e; }
    else if ((e -= N2) < N2) { src = Wo2; dst = wo2; i = e; }
    else if ((e -= N2) < N4) { src = Wo;  dst = wo;  i = e; }
    else if ((e -= N4) < N4) { src = Wpk; dst = wpk; i = e; }
    else if ((e -= N4) < N4) { src = Wpq; dst = wpq; i = e; }
    else if ((e -= N4) < N7) { src = rel_emb; dst = rel; i = e; }
    else {
        e -= N7;
        if (e < N8) {
            #pragma unroll
            for (int t = 0; t < 4; t++) {
                long idx = e + t;
                int l = (int)(idx / D3), col = (int)(idx - (long)l * D3);
                const float* s2; int c;
                if (col < DMODEL)        { s2 = bq; c = col; }
                else if (col < 2*DMODEL) { s2 = bk; c = col - DMODEL; }
                else                     { s2 = bv; c = col - 2*DMODEL; }
                bqkv[idx] = s2[(size_t)l * DMODEL + c];
            }
        }
        return;
    }
    float4 v = *reinterpret_cast<const float4*>(src + i);
    dst[i] = __float2half(v.x); dst[i+1] = __float2half(v.y);
    dst[i+2] = __float2half(v.z); dst[i+3] = __float2half(v.w);
}

// -------------------- warp reductions --------------------
__device__ __forceinline__ float warp_sum(float v) {
    #pragma unroll
    for (int o = 16; o > 0; o >>= 1) v += __shfl_xor_sync(0xffffffffu, v, o);
    return v;
}
__device__ __forceinline__ float warp_max(float v) {
    #pragma unroll
    for (int o = 16; o > 0; o >>= 1) v = fmaxf(v, __shfl_xor_sync(0xffffffffu, v, o));
    return v;
}

// ------------- warp-per-row softmax -----------
__global__ void combine_softmax(__half* __restrict__ s1, const __half* __restrict__ c2p,
                                const __half* __restrict__ p2c, const int* __restrict__ amask)
{
    const int warp = threadIdx.x >> 5, lane = threadIdx.x & 31;
    const int q = blockIdx.x * 8 + warp;
    const int z = blockIdx.y, b = z >> 3;
    const float inv_scale = 0.05892556509887896f;   // 1/sqrt(288)
    __half* srow = s1 + ((size_t)z * SEQ + q) * SEQ;
    const __half* crow = c2p + ((size_t)z * SEQ + q) * PPOS;
    const __half* pz   = p2c + (size_t)z * SEQ * PPOS;
    const int mq = amask[b * SEQ + q];

    float vals[16];
    #pragma unroll
    for (int i = 0; i < 16; i++) {
        int k = lane + 32 * i;
        int d = q - k + SPAN;
        float s = (__half2float(srow[k]) + __half2float(crow[d])
                 + __half2float(pz[(size_t)k * PPOS + d])) * inv_scale;
        int mk = amask[b * SEQ + k];
        vals[i] = (mq * mk > 0) ? s : NEGF;
    }
    float mx = vals[0];
    #pragma unroll
    for (int i = 1; i < 16; i++) mx = fmaxf(mx, vals[i]);
    mx = warp_max(mx);
    float sum = 0.f;
    #pragma unroll
    for (int i = 0; i < 16; i++) { vals[i] = __expf(vals[i] - mx); sum += vals[i]; }
    float inv = 1.0f / warp_sum(sum);
    #pragma unroll
    for (int i = 0; i < 16; i++) srow[lane + 32 * i] = __float2half(vals[i] * inv);
}

// ---------------- LayerNorm: warp-per-row ----------------
__global__ void add_ln(const __half* __restrict__ a, const float* __restrict__ res,
                       const float* __restrict__ g, const float* __restrict__ beta,
                       float* __restrict__ outF, __half* __restrict__ outH)
{
    const int warp = threadIdx.x >> 5, lane = threadIdx.x & 31;
    const int row = blockIdx.x * 8 + warp;
    const __half* ar = a + (size_t)row * DMODEL;
    const float*  rr = res + (size_t)row * DMODEL;
    float v[24];
    float partial = 0.f;
    #pragma unroll
    for (int i = 0; i < 6; i++) {
        int j = lane * 4 + i * 128;
        uint2 hu = *reinterpret_cast<const uint2*>(ar + j);
        __half2 h0 = *reinterpret_cast<__half2*>(&hu.x);
        __half2 h1 = *reinterpret_cast<__half2*>(&hu.y);
        float4 rv = *reinterpret_cast<const float4*>(rr + j);
        v[4*i+0] = __half2float(h0.x) + rv.x;
        v[4*i+1] = __half2float(h0.y) + rv.y;
        v[4*i+2] = __half2float(h1.x) + rv.z;
        v[4*i+3] = __half2float(h1.y) + rv.w;
        partial += v[4*i+0] + v[4*i+1] + v[4*i+2] + v[4*i+3];
    }
    float mean = warp_sum(partial) * (1.0f / DMODEL);
    float p2 = 0.f;
    #pragma unroll
    for (int i = 0; i < 24; i++) { float d = v[i] - mean; p2 += d * d; }
    float rstd = rsqrtf(warp_sum(p2) * (1.0f / DMODEL) + LN_EPS);
    float* oF = outF + (size_t)row * DMODEL;
    __half* oH = outH + (size_t)row * DMODEL;
    #pragma unroll
    for (int i = 0; i < 6; i++) {
        int j = lane * 4 + i * 128;
        float4 o;
        o.x = (v[4*i+0] - mean) * rstd * g[j]   + beta[j];
        o.y = (v[4*i+1] - mean) * rstd * g[j+1] + beta[j+1];
        o.z = (v[4*i+2] - mean) * rstd * g[j+2] + beta[j+2];
        o.w = (v[4*i+3] - mean) * rstd * g[j+3] + beta[j+3];
        *reinterpret_cast<float4*>(oF + j) = o;
        __half2 h0 = __floats2half2_rn(o.x, o.y), h1 = __floats2half2_rn(o.z, o.w);
        uint2 hu;
        hu.x = *reinterpret_cast<uint32_t*>(&h0);
        hu.y = *reinterpret_cast<uint32_t*>(&h1);
        *reinterpret_cast<uint2*>(oH + j) = hu;
    }
}

__global__ void embed_ln(const float* __restrict__ x, const float* __restrict__ pos,
                         const float* __restrict__ g, const float* __restrict__ beta,
                         const int* __restrict__ amask, float* __restrict__ outF,
                         __half* __restrict__ outH)
{
    const int warp = threadIdx.x >> 5, lane = threadIdx.x & 31;
    const int row = blockIdx.x * 8 + warp;
    const int s = row & (SEQ - 1);
    const float* xr = x + (size_t)row * DMODEL;
    const float* pr = pos + (size_t)s * DMODEL;
    float v[24];
    float partial = 0.f;
    #pragma unroll
    for (int i = 0; i < 6; i++) {
        int j = lane * 4 + i * 128;
        float4 xv = *reinterpret_cast<const float4*>(xr + j);
        float4 pv = *reinterpret_cast<const float4*>(pr + j);
        v[4*i+0] = xv.x + pv.x; v[4*i+1] = xv.y + pv.y;
        v[4*i+2] = xv.z + pv.z; v[4*i+3] = xv.w + pv.w;
        partial += v[4*i+0] + v[4*i+1] + v[4*i+2] + v[4*i+3];
    }
    float mean = warp_sum(partial) * (1.0f / DMODEL);
    float p2 = 0.f;
    #pragma unroll
    for (int i = 0; i < 24; i++) { float d = v[i] - mean; p2 += d * d; }
    float rstd = rsqrtf(warp_sum(p2) * (1.0f / DMODEL) + LN_EPS);
    float mf = (float)amask[row];
    float* oF = outF + (size_t)row * DMODEL;
    __half* oH = outH + (size_t)row * DMODEL;
    #pragma unroll
    for (int i = 0; i < 6; i++) {
        int j = lane * 4 + i * 128;
        float4 o;
        o.x = ((v[4*i+0] - mean) * rstd * g[j]   + beta[j])   * mf;
        o.y = ((v[4*i+1] - mean) * rstd * g[j+1] + beta[j+1]) * mf;
        o.z = ((v[4*i+2] - mean) * rstd * g[j+2] + beta[j+2]) * mf;
        o.w = ((v[4*i+3] - mean) * rstd * g[j+3] + beta[j+3]) * mf;
        *reinterpret_cast<float4*>(oF + j) = o;
        __half2 h0 = __floats2half2_rn(o.x, o.y), h1 = __floats2half2_rn(o.z, o.w);
        uint2 hu;
        hu.x = *reinterpret_cast<uint32_t*>(&h0);
        hu.y = *reinterpret_cast<uint32_t*>(&h1);
        *reinterpret_cast<uint2*>(oH + j) = hu;
    }
}

// ==================================== launcher ====================================
static inline int pgrid(int tiles, int cap) { return tiles < cap ? tiles : cap; }

extern "C" void kernel_launch(void* const* d_in, const int* in_sizes, int n_in,
                              void* d_out, int out_size)
{
    const float* x       = (const float*)d_in[0];
    const float* pos_emb = (const float*)d_in[1];
    const float* rel_emb = (const float*)d_in[2];
    const float* ln_e_g  = (const float*)d_in[3];
    const float* ln_e_b  = (const float*)d_in[4];
    const float* Wq  = (const float*)d_in[5];
    const float* bq  = (const float*)d_in[6];
    const float* Wk  = (const float*)d_in[7];
    const float* bk  = (const float*)d_in[8];
    const float* Wv  = (const float*)d_in[9];
    const float* bv  = (const float*)d_in[10];
    const float* Wo  = (const float*)d_in[11];
    const float* bo  = (const float*)d_in[12];
    const float* Wpk = (const float*)d_in[13];
    const float* bpk = (const float*)d_in[14];
    const float* Wpq = (const float*)d_in[15];
    const float* bpq = (const float*)d_in[16];
    const float* ln1g = (const float*)d_in[17];
    const float* ln1b = (const float*)d_in[18];
    const float* Wi   = (const float*)d_in[19];
    const float* bi   = (const float*)d_in[20];
    const float* Wo2  = (const float*)d_in[21];
    const float* bo2  = (const float*)d_in[22];
    const float* ln2g = (const float*)d_in[23];
    const float* ln2b = (const float*)d_in[24];
    const int*   amask = (const int*)d_in[25];

    float *h32, *bqkv;
    __half *h16, *qkv, *ctx, *tmp, *wqkv, *wi, *wo2, *wo, *wpk, *wpq, *rel;
    __half *pk, *pq, *s1, *c2p, *p2c, *ffn;
    cudaGetSymbolAddress((void**)&h32,  g_h32);
    cudaGetSymbolAddress((void**)&h16,  g_h16);
    cudaGetSymbolAddress((void**)&qkv,  g_qkv);
    cudaGetSymbolAddress((void**)&ctx,  g_ctx);
    cudaGetSymbolAddress((void**)&tmp,  g_tmp);
    cudaGetSymbolAddress((void**)&wqkv, g_wqkv);
    cudaGetSymbolAddress((void**)&bqkv, g_bqkv);
    cudaGetSymbolAddress((void**)&wi,   g_wi);
    cudaGetSymbolAddress((void**)&wo2,  g_wo2);
    cudaGetSymbolAddress((void**)&wo,   g_wo);
    cudaGetSymbolAddress((void**)&wpk,  g_wpk);
    cudaGetSymbolAddress((void**)&wpq,  g_wpq);
    cudaGetSymbolAddress((void**)&rel,  g_rel);
    cudaGetSymbolAddress((void**)&pk,   g_pk);
    cudaGetSymbolAddress((void**)&pq,   g_pq);
    cudaGetSymbolAddress((void**)&s1,   g_s1);
    cudaGetSymbolAddress((void**)&c2p,  g_c2p);
    cudaGetSymbolAddress((void**)&p2c,  g_p2c);
    cudaGetSymbolAddress((void**)&ffn,  g_ffn);

    const long DD = (long)DMODEL * DMODEL;
    const long S2 = (long)SEQ * SEQ;
    const long SD3 = (long)SEQ * D3;
    const long PD = (long)PPOS * DMODEL;
    const int CAP = 296;
    const int CAP4 = 592;

    const int SM_NN128 = 4 * 128 * 80 + 4 * 32 * 272;   // 75776
    const int SM_ATT   = 4 * 128 * 80 + 4 * 128 * 80;   // 81920
    const int SM_NN96  = 4 * 128 * 80 + 4 * 32 * 208;   // 67584
    const int SM_NN64  = 4 * 64 * 80 + 4 * 32 * 272;    // 55296
    cudaFuncSetAttribute(hgemm<128,128,8,false>, cudaFuncAttributeMaxDynamicSharedMemorySize, SM_NN128);
    cudaFuncSetAttribute(hgemm_att3,             cudaFuncAttributeMaxDynamicSharedMemorySize, SM_ATT);
    cudaFuncSetAttribute(hgemm<128,96,6,false>,  cudaFuncAttributeMaxDynamicSharedMemorySize, SM_NN96);
    cudaFuncSetAttribute(hgemm<64,128,4,false>,  cudaFuncAttributeMaxDynamicSharedMemorySize, SM_NN64);

    // ---- fused prologue (1 launch) ----
    {
        long total = (long)NLAYER*DMODEL*D3 + 2L*NLAYER*DMODEL*FF + 3L*NLAYER*DD
                   + (long)PPOS*DMODEL + (long)NLAYER*D3;
        prep_all<<<(unsigned)((total / 4 + 255) / 256), 256>>>(
            Wq, Wk, Wv, bq, bk, bv, Wi, Wo2, Wo, Wpk, Wpq, rel_emb,
            wqkv, bqkv, wi, wo2, wo, wpk, wpq, rel);
    }
    embed_ln<<<NTOK/8, 256>>>(x, pos_emb, ln_e_g, ln_e_b, amask, h32, h16);

    // pos projections, all layers (z = layer): 48 tiles/z
    hgemm<128,128,8,false><<<pgrid(288, CAP), 256, SM_NN128>>>(
        rel, wpk, bpk, pk, DMODEL, DMODEL, DMODEL, DMODEL,
        0, 0, 0, DD, DMODEL, 0, PD, 0, 288, 48, 6, 0);
    hgemm<128,128,8,false><<<pgrid(288, CAP), 256, SM_NN128>>>(
        rel, wpq, bpq, pq, DMODEL, DMODEL, DMODEL, DMODEL,
        0, 0, 0, DD, DMODEL, 0, PD, 0, 288, 48, 6, 0);

    for (int l = 0; l < NLAYER; l++) {
        // fused QKV: 576 tiles
        hgemm<128,128,8,false><<<pgrid(576, CAP), 256, SM_NN128>>>(
            h16, wqkv + (size_t)l * DMODEL * D3, bqkv + (size_t)l * D3, qkv,
            DMODEL, DMODEL, D3, D3, 0,0,0,0,0, 0,0, 0, 576, 576, 18, 0);

        // merged attention trio: scores + c2p + p2c, 3584 tiles, one launch
        hgemm_att3<<<pgrid(3584, CAP), 256, SM_ATT>>>(
            qkv, pk + (size_t)l * PD, pq + (size_t)l * PD, s1, c2p, p2c, 3584);

        combine_softmax<<<dim3(SEQ/8, ZBAT), 256>>>(s1, c2p, p2c, amask);

        // ctx = probs @ V -> [b, q, h*96+d]
        hgemm<128,96,6,false><<<pgrid(256, CAP), 192, SM_NN96>>>(
            s1, qkv + 2*DMODEL, nullptr, ctx, SEQ, SEQ, D3, DMODEL,
            8*S2, S2, SD3, DH, 0, (long)SEQ*DMODEL, DH, 0, 256, 4, 1, 0);

        // attn out proj: BM=64 -> 384 tiles
        hgemm<64,128,4,false><<<pgrid(384, CAP4), 128, SM_NN64>>>(
            ctx, wo + (size_t)l*DD, bo + (size_t)l*DMODEL, tmp,
            DMODEL, DMODEL, DMODEL, DMODEL, 0,0,0,0,0, 0,0, 0, 384, 384, 6, 0);
        add_ln<<<NTOK/8, 256>>>(tmp, h32, ln1g + (size_t)l*DMODEL, ln1b + (size_t)l*DMODEL, h32, h16);

        // FFN1 (gelu): 768 tiles
        hgemm<128,128,8,false><<<pgrid(768, CAP), 256, SM_NN128>>>(
            h16, wi + (size_t)l*DMODEL*FF, bi + (size_t)l*FF, ffn,
            DMODEL, DMODEL, FF, FF, 0,0,0,0,0, 0,0, 1, 768, 768, 24, 0);
        // FFN2: K=3072, BM=64 -> 384 tiles
        hgemm<64,128,4,false><<<pgrid(384, CAP4), 128, SM_NN64>>>(
            ffn, wo2 + (size_t)l*FF*DMODEL, bo2 + (size_t)l*DMODEL, tmp,
            FF, FF, DMODEL, DMODEL, 0,0,0,0,0, 0,0, 0, 384, 384, 6, 0);

        float* outF = (l == NLAYER - 1) ? (float*)d_out : h32;
        add_ln<<<NTOK/8, 256>>>(tmp, h32, ln2g + (size_t)l*DMODEL, ln2b + (size_t)l*DMODEL, outF, h16);
    }
}